// round 5
// baseline (speedup 1.0000x reference)
#include <cuda_runtime.h>
#include <cstdint>

#define H 256

#define MAXV 100000
#define MAXE 150000
#define MAXL 80000
#define MAXF 60000
#define MAXPAIR 800000

// CSR region offsets (3 independent conv graphs in one buffer set)
#define OFF0 0
#define OFF1 (MAXE + 1)
#define OFF2 (MAXE + 1 + MAXL + 1)
#define CSRTOT (MAXE + MAXL + MAXF + 3)

// scratch
__device__ float    g_v[(size_t)MAXV * H];
__device__ float    g_e[(size_t)MAXE * H];
__device__ float    g_eo[(size_t)MAXE * H];
__device__ float    g_l[(size_t)MAXL * H];
__device__ float    g_f[(size_t)MAXF * H];
__device__ float    g_mh[(size_t)MAXE * H];
__device__ int      g_cnt[CSRTOT];
__device__ int      g_off[CSRTOT];
__device__ int      g_cur[CSRTOT];
__device__ int      g_col[MAXPAIR];
__device__ int      g_bsum[192];

// ---------- helpers ----------
__device__ __forceinline__ float leaky(float a) { return a >= 0.f ? a : 0.01f * a; }

__device__ __forceinline__ void mma_tf32(float c[4], const unsigned a[4], const unsigned b[2]) {
    asm volatile(
        "mma.sync.aligned.m16n8k8.row.col.f32.tf32.tf32.f32 "
        "{%0,%1,%2,%3},{%4,%5,%6,%7},{%8,%9},{%0,%1,%2,%3};"
        : "+f"(c[0]), "+f"(c[1]), "+f"(c[2]), "+f"(c[3])
        : "r"(a[0]), "r"(a[1]), "r"(a[2]), "r"(a[3]), "r"(b[0]), "r"(b[1]));
}

__device__ __forceinline__ void cp16(float* s, const float* g, bool valid) {
    unsigned saddr = (unsigned)__cvta_generic_to_shared(s);
    int sz = valid ? 16 : 0;
    asm volatile("cp.async.cg.shared.global [%0], [%1], 16, %2;" :: "r"(saddr), "l"(g), "r"(sz));
}
__device__ __forceinline__ void cp_commit() { asm volatile("cp.async.commit_group;"); }
template<int N> __device__ __forceinline__ void cp_wait() { asm volatile("cp.async.wait_group %0;" :: "n"(N)); }

// ---------- embedding: compile-time widths, 32 rows/block, thread = 8 rows x 4 cols ----------
template<int W0, int W1, int W2>
__global__ void embed_kernel(const float* __restrict__ s0,
                             const float* __restrict__ s1,
                             const float* __restrict__ s2,
                             const float* __restrict__ W, const float* __restrict__ bias,
                             float* __restrict__ out, int n) {
    const int RB = 32;
    const int IN = W0 + W1 + W2;
    int row0 = blockIdx.x * RB;
    int tid = threadIdx.x;
    int cg = tid & 63, rg = tid >> 6;     // 64 col-groups (float4), 4 row-groups of 8
    __shared__ float xs[RB][IN + 1];

    for (int i = tid; i < RB * IN; i += 256) {
        int r = i / IN, k = i % IN;
        int row = row0 + r;
        float v = 0.f;
        if (row < n) {
            if (k < W0)            v = s0[(size_t)row * W0 + k];
            else if (k < W0 + W1)  v = s1[(size_t)row * W1 + (k - W0)];
            else                   v = s2[row];
        }
        xs[r][k] = v;
    }
    __syncthreads();

    float4 b = reinterpret_cast<const float4*>(bias)[cg];
    float4 acc[8];
#pragma unroll
    for (int q = 0; q < 8; q++) acc[q] = b;
#pragma unroll
    for (int k = 0; k < IN; k++) {
        float4 w = reinterpret_cast<const float4*>(W + (size_t)k * H)[cg];
#pragma unroll
        for (int q = 0; q < 8; q++) {
            float xv = xs[rg * 8 + q][k];
            acc[q].x += xv * w.x; acc[q].y += xv * w.y;
            acc[q].z += xv * w.z; acc[q].w += xv * w.w;
        }
    }
#pragma unroll
    for (int q = 0; q < 8; q++) {
        int row = row0 + rg * 8 + q;
        if (row < n) {
            float4 o = make_float4(leaky(acc[q].x), leaky(acc[q].y),
                                   leaky(acc[q].z), leaky(acc[q].w));
            reinterpret_cast<float4*>(out + (size_t)row * H)[cg] = o;
        }
    }
}

// ---------- batched CSR build over 3 conv graphs ----------
__global__ void count_all_kernel(const int* __restrict__ d0, int n0,
                                 const int* __restrict__ d1, int n1,
                                 const int* __restrict__ d2, int n2,
                                 int* __restrict__ cnt) {
    int i = blockIdx.x * blockDim.x + threadIdx.x;
    if (i < n0)                atomicAdd(&cnt[OFF0 + d0[i]], 1);
    else if (i < n0 + n1)      atomicAdd(&cnt[OFF1 + d1[i - n0]], 1);
    else if (i < n0 + n1 + n2) atomicAdd(&cnt[OFF2 + d2[i - n0 - n1]], 1);
}

// phase1: per-block (4096 elems) local exclusive scan + block sums; y = conv id
__global__ void scan_phase1(const int* __restrict__ cnt, int na, int nb_, int nc,
                            int* __restrict__ off, int* __restrict__ bsum) {
    __shared__ int wsum[32];
    int conv = blockIdx.y;
    int n = (conv == 0) ? na : (conv == 1) ? nb_ : nc;
    if (blockIdx.x * 4096 >= n) return;
    int base0 = (conv == 0) ? OFF0 : (conv == 1) ? OFF1 : OFF2;
    const int* c = cnt + base0;
    int* o = off + base0;
    int tid = threadIdx.x, lane = tid & 31, wid = tid >> 5;
    int base = blockIdx.x * 4096 + tid * 4;
    int v0 = (base     < n) ? c[base]     : 0;
    int v1 = (base + 1 < n) ? c[base + 1] : 0;
    int v2 = (base + 2 < n) ? c[base + 2] : 0;
    int v3 = (base + 3 < n) ? c[base + 3] : 0;
    int s = v0 + v1 + v2 + v3;
    int x = s;
#pragma unroll
    for (int d = 1; d < 32; d <<= 1) {
        int y = __shfl_up_sync(~0u, x, d);
        if (lane >= d) x += y;
    }
    if (lane == 31) wsum[wid] = x;
    __syncthreads();
    if (wid == 0) {
        int w = wsum[lane];
#pragma unroll
        for (int d = 1; d < 32; d <<= 1) {
            int y = __shfl_up_sync(~0u, w, d);
            if (lane >= d) w += y;
        }
        wsum[lane] = w;
    }
    __syncthreads();
    int run = x - s + (wid ? wsum[wid - 1] : 0);
    if (base     < n) o[base]     = run; run += v0;
    if (base + 1 < n) o[base + 1] = run; run += v1;
    if (base + 2 < n) o[base + 2] = run; run += v2;
    if (base + 3 < n) o[base + 3] = run;
    if (tid == 0) bsum[conv * 64 + blockIdx.x] = wsum[31];
}

// phase2: scan each conv's block sums (<=64)
__global__ void scan_phase2(int* __restrict__ bsum, int na, int nb_, int nc,
                            int* __restrict__ off) {
    __shared__ int tmp[64];
    int conv = blockIdx.x;
    int n = (conv == 0) ? na : (conv == 1) ? nb_ : nc;
    int base0 = (conv == 0) ? OFF0 : (conv == 1) ? OFF1 : OFF2;
    int* bs = bsum + conv * 64;
    int nb = (n + 4095) / 4096;
    int tid = threadIdx.x;
    int v = (tid < nb) ? bs[tid] : 0;
    tmp[tid] = v;
    __syncthreads();
    int x = v;
    for (int d = 1; d < 64; d <<= 1) {
        int y = (tid >= d) ? tmp[tid - d] : 0;
        __syncthreads();
        x += y;
        tmp[tid] = x;
        __syncthreads();
    }
    if (tid < nb) bs[tid] = x - v;
    if (tid == 63) off[base0 + n] = x;
}

// phase3: add block offsets, copy to cur
__global__ void scan_phase3(int* __restrict__ off, const int* __restrict__ bsum,
                            int na, int nb_, int nc, int* __restrict__ cur) {
    int conv = blockIdx.y;
    int n = (conv == 0) ? na : (conv == 1) ? nb_ : nc;
    int i = blockIdx.x * blockDim.x + threadIdx.x;
    if (i >= n) return;
    int base0 = (conv == 0) ? OFF0 : (conv == 1) ? OFF1 : OFF2;
    int o = off[base0 + i] + bsum[conv * 64 + (i >> 12)];
    off[base0 + i] = o;
    cur[base0 + i] = o;
}

__global__ void fill_all_kernel(const int* __restrict__ e0, int n0,
                                const int* __restrict__ e1, int n1,
                                const int* __restrict__ e2, int n2,
                                int* __restrict__ cur, int* __restrict__ col) {
    int i = blockIdx.x * blockDim.x + threadIdx.x;
    const int* idx; int j, base0, cbase;
    if (i < n0)                { idx = e0; j = i;           base0 = OFF0; cbase = 0; }
    else if (i < n0 + n1)      { idx = e1; j = i - n0;      base0 = OFF1; cbase = n0; }
    else if (i < n0 + n1 + n2) { idx = e2; j = i - n0 - n1; base0 = OFF2; cbase = n0 + n1; }
    else return;
    int d = idx[j];                 // dst (row 0)
    int s = idx[j + ((idx == e0) ? n0 : (idx == e1) ? n1 : n2)];  // src (row 1)
    int pos = atomicAdd(&cur[base0 + d], 1);
    col[cbase + pos] = s;
}

// ---------- fused segment-min + (x_dst - min) ----------
__global__ void segmin_csr_kernel(const int* __restrict__ off, const int* __restrict__ col,
                                  int n_dst,
                                  const float* __restrict__ xsrc,
                                  const float* __restrict__ xdst,
                                  float* __restrict__ mh) {
    int w = (blockIdx.x * blockDim.x + threadIdx.x) >> 5;
    int lane = threadIdx.x & 31;
    if (w >= n_dst) return;
    int beg = off[w], end = off[w + 1];
    const float INF = __int_as_float(0x7f800000);
    float4 m0 = make_float4(INF, INF, INF, INF);
    float4 m1 = m0;
    for (int j = beg; j < end; j++) {
        int s = col[j];
        const float4* r = reinterpret_cast<const float4*>(xsrc + (size_t)s * H);
        float4 v0 = r[lane];
        float4 v1 = r[lane + 32];
        m0.x = fminf(m0.x, v0.x); m0.y = fminf(m0.y, v0.y);
        m0.z = fminf(m0.z, v0.z); m0.w = fminf(m0.w, v0.w);
        m1.x = fminf(m1.x, v1.x); m1.y = fminf(m1.y, v1.y);
        m1.z = fminf(m1.z, v1.z); m1.w = fminf(m1.w, v1.w);
    }
    const float4* xd = reinterpret_cast<const float4*>(xdst + (size_t)w * H);
    float4 d0 = xd[lane], d1 = xd[lane + 32];
    float4 o0, o1;
    if (beg < end) {
        o0 = make_float4(d0.x - m0.x, d0.y - m0.y, d0.z - m0.z, d0.w - m0.w);
        o1 = make_float4(d1.x - m1.x, d1.y - m1.y, d1.z - m1.z, d1.w - m1.w);
    } else {
        o0 = make_float4(0.f, 0.f, 0.f, 0.f);
        o1 = o0;
    }
    float4* mo = reinterpret_cast<float4*>(mh + (size_t)w * H);
    mo[lane] = o0;
    mo[lane + 32] = o1;
}

// ---------- tensor-core conv GEMM: 3-stage cp.async, 1 sync/iter ----------
#define BM 128
#define BN 128
#define BK 32
#define ASTR 36
#define BSTR 136
#define ASZ (BM * ASTR)
#define BSZ (BK * BSTR)
#define STAGE (ASZ + BSZ)
#define SMEM_BYTES (STAGE * 3 * 4)

__global__ __launch_bounds__(256) void conv_gemm_tc(const float* __restrict__ x,
                                                    const float* __restrict__ mh,
                                                    const float* __restrict__ W,
                                                    const float* __restrict__ bias,
                                                    float* __restrict__ out, int M) {
    extern __shared__ float sm[];
    int tid = threadIdx.x;
    int warp = tid >> 5, lane = tid & 31;
    int g = lane >> 2, t = lane & 3;
    int wr = warp >> 2, wc = warp & 3;
    int m_w = wr * 64, n_w = wc * 32;
    int bm = blockIdx.x * BM, bn = blockIdx.y * BN;

    int arow = tid >> 3, ac4 = (tid & 7) * 4;
    int brow = tid >> 5, bc4 = (tid & 31) * 4;

    float c[4][4][4];
#pragma unroll
    for (int i = 0; i < 4; i++)
#pragma unroll
        for (int j = 0; j < 4; j++)
#pragma unroll
            for (int q = 0; q < 4; q++) c[i][j][q] = 0.f;

    auto prefetch = [&](int k0, int stg) {
        const float* Ab = (k0 < 256) ? x : mh;
        int kk = k0 & 255;
        float* Ad = sm + stg * STAGE;
        float* Bd = Ad + ASZ;
#pragma unroll
        for (int r = 0; r < 4; r++) {
            int row = arow + r * 32;
            bool v = (bm + row) < M;
            const float* gp = Ab + (size_t)(v ? bm + row : 0) * H + kk + ac4;
            cp16(Ad + row * ASTR + ac4, gp, v);
        }
#pragma unroll
        for (int r = 0; r < 4; r++) {
            int row = brow + r * 8;
            cp16(Bd + row * BSTR + bc4, W + (size_t)(k0 + row) * H + bn + bc4, true);
        }
        cp_commit();
    };

    prefetch(0, 0);
    prefetch(BK, 1);

    for (int it = 0; it < 16; it++) {
        if (it < 15) cp_wait<1>(); else cp_wait<0>();
        __syncthreads();
        if (it < 14) prefetch((it + 2) * BK, (it + 2) % 3);

        const float* Asb = sm + (it % 3) * STAGE;
        const float* Bsb = Asb + ASZ;
#pragma unroll
        for (int ks = 0; ks < 4; ks++) {
            int kb = ks * 8;
            unsigned a[4][4], b[4][2];
#pragma unroll
            for (int i = 0; i < 4; i++) {
                int mb = m_w + i * 16;
                a[i][0] = __float_as_uint(Asb[(mb + g) * ASTR + kb + t]);
                a[i][1] = __float_as_uint(Asb[(mb + g + 8) * ASTR + kb + t]);
                a[i][2] = __float_as_uint(Asb[(mb + g) * ASTR + kb + t + 4]);
                a[i][3] = __float_as_uint(Asb[(mb + g + 8) * ASTR + kb + t + 4]);
            }
#pragma unroll
            for (int j = 0; j < 4; j++) {
                int nb = n_w + j * 8;
                b[j][0] = __float_as_uint(Bsb[(kb + t) * BSTR + nb + g]);
                b[j][1] = __float_as_uint(Bsb[(kb + t + 4) * BSTR + nb + g]);
            }
#pragma unroll
            for (int i = 0; i < 4; i++)
#pragma unroll
                for (int j = 0; j < 4; j++) mma_tf32(c[i][j], a[i], b[j]);
        }
    }

    // epilogue: out = x + leaky(c + bias)
#pragma unroll
    for (int i = 0; i < 4; i++) {
        int r0 = bm + m_w + i * 16 + g;
        int r1 = r0 + 8;
#pragma unroll
        for (int j = 0; j < 4; j++) {
            int col = bn + n_w + j * 8 + t * 2;
            float b0 = bias[col], b1 = bias[col + 1];
            if (r0 < M) {
                size_t o = (size_t)r0 * H + col;
                out[o]     = x[o]     + leaky(c[i][j][0] + b0);
                out[o + 1] = x[o + 1] + leaky(c[i][j][1] + b1);
            }
            if (r1 < M) {
                size_t o = (size_t)r1 * H + col;
                out[o]     = x[o]     + leaky(c[i][j][2] + b0);
                out[o + 1] = x[o + 1] + leaky(c[i][j][3] + b1);
            }
        }
    }
}

// ---------- launch ----------
static inline int cdiv(int a, int b) { return (a + b - 1) / b; }

extern "C" void kernel_launch(void* const* d_in, const int* in_sizes, int n_in,
                              void* d_out, int out_size) {
    const float* vp  = (const float*)d_in[0];
    const float* ec  = (const float*)d_in[1];
    const float* ecp = (const float*)d_in[2];
    const float* ecf = (const float*)d_in[3];
    const float* lt  = (const float*)d_in[4];
    const float* fs  = (const float*)d_in[5];
    const float* fsp = (const float*)d_in[6];
    const float* fsf = (const float*)d_in[7];
    const int* ev = (const int*)d_in[8];
    const int* le = (const int*)d_in[9];
    const int* fl = (const int*)d_in[10];
    const float* Wv = (const float*)d_in[11]; const float* bv = (const float*)d_in[12];
    const float* We = (const float*)d_in[13]; const float* be = (const float*)d_in[14];
    const float* Wl = (const float*)d_in[15]; const float* bl = (const float*)d_in[16];
    const float* Wf = (const float*)d_in[17]; const float* bf = (const float*)d_in[18];
    const float* Wve = (const float*)d_in[19]; const float* bve = (const float*)d_in[20];
    const float* Wel = (const float*)d_in[21]; const float* bel = (const float*)d_in[22];
    const float* Wlf = (const float*)d_in[23]; const float* blf = (const float*)d_in[24];

    int NVn = in_sizes[0] / 3;
    int NEn = in_sizes[1] / 8;
    int NLn = in_sizes[4] / 10;
    int NFn = in_sizes[5] / 12;
    int nEV = in_sizes[8] / 2;
    int nLE = in_sizes[9] / 2;
    int nFL = in_sizes[10] / 2;

    float *pv, *pe, *peo, *pl, *pf, *pmh;
    int *pcnt, *poff, *pcur, *pcol, *pbsum;
    cudaGetSymbolAddress((void**)&pv,    g_v);
    cudaGetSymbolAddress((void**)&pe,    g_e);
    cudaGetSymbolAddress((void**)&peo,   g_eo);
    cudaGetSymbolAddress((void**)&pl,    g_l);
    cudaGetSymbolAddress((void**)&pf,    g_f);
    cudaGetSymbolAddress((void**)&pmh,   g_mh);
    cudaGetSymbolAddress((void**)&pcnt,  g_cnt);
    cudaGetSymbolAddress((void**)&poff,  g_off);
    cudaGetSymbolAddress((void**)&pcur,  g_cur);
    cudaGetSymbolAddress((void**)&pcol,  g_col);
    cudaGetSymbolAddress((void**)&pbsum, g_bsum);

    cudaFuncSetAttribute(conv_gemm_tc, cudaFuncAttributeMaxDynamicSharedMemorySize, SMEM_BYTES);

    int nPairTot = nEV + nLE + nFL;
    int nmax = NEn;  // largest dst count

    // --- batched CSR build for all 3 convs ---
    cudaMemsetAsync(pcnt, 0, (size_t)CSRTOT * sizeof(int));
    count_all_kernel<<<cdiv(nPairTot, 256), 256>>>(ev, nEV, le, nLE, fl, nFL, pcnt);
    {
        dim3 g1(cdiv(nmax, 4096), 3);
        scan_phase1<<<g1, 1024>>>(pcnt, NEn, NLn, NFn, poff, pbsum);
        scan_phase2<<<3, 64>>>(pbsum, NEn, NLn, NFn, poff);
        dim3 g3(cdiv(nmax, 256), 3);
        scan_phase3<<<g3, 256>>>(poff, pbsum, NEn, NLn, NFn, pcur);
    }
    fill_all_kernel<<<cdiv(nPairTot, 256), 256>>>(ev, nEV, le, nLE, fl, nFL, pcur, pcol);

    // --- embeddings ---
    embed_kernel<3, 0, 0><<<cdiv(NVn, 32), 256>>>(vp, nullptr, nullptr, Wv, bv, pv, NVn);
    embed_kernel<8, 6, 1><<<cdiv(NEn, 32), 256>>>(ec, ecp, ecf, We, be, pe, NEn);
    embed_kernel<10, 0, 0><<<cdiv(NLn, 32), 256>>>(lt, nullptr, nullptr, Wl, bl, pl, NLn);
    embed_kernel<12, 4, 1><<<cdiv(NFn, 32), 256>>>(fs, fsp, fsf, Wf, bf, pf, NFn);

    // --- conv 1: vertices -> edges ---
    segmin_csr_kernel<<<cdiv(NEn * 32, 256), 256>>>(poff + OFF0, pcol, NEn, pv, pe, pmh);
    {
        dim3 g(cdiv(NEn, BM), 2);
        conv_gemm_tc<<<g, 256, SMEM_BYTES>>>(pe, pmh, Wve, bve, peo, NEn);
    }
    // --- conv 2: edges -> loops (output reuses g_v) ---
    segmin_csr_kernel<<<cdiv(NLn * 32, 256), 256>>>(poff + OFF1, pcol + nEV, NLn, peo, pl, pmh);
    {
        dim3 g(cdiv(NLn, BM), 2);
        conv_gemm_tc<<<g, 256, SMEM_BYTES>>>(pl, pmh, Wel, bel, pv, NLn);
    }
    // --- conv 3: loops -> faces (output = d_out) ---
    segmin_csr_kernel<<<cdiv(NFn * 32, 256), 256>>>(poff + OFF2, pcol + nEV + nLE, NFn, pv, pf, pmh);
    {
        dim3 g(cdiv(NFn, BM), 2);
        conv_gemm_tc<<<g, 256, SMEM_BYTES>>>(pf, pmh, Wlf, blf, (float*)d_out, NFn);
    }
}

// round 7
// speedup vs baseline: 1.1507x; 1.1507x over previous
#include <cuda_runtime.h>
#include <cuda_fp16.h>
#include <cstdint>

#define H 256

#define MAXV 100000
#define MAXE 150000
#define MAXL 80000
#define MAXF 60000
#define MAXPAIR 800000

#define OFF0 0
#define OFF1 (MAXE + 1)
#define OFF2 (MAXE + 1 + MAXL + 1)
#define CSRTOT (MAXE + MAXL + MAXF + 3)

// scratch
__device__ float    g_v[(size_t)MAXV * H];
__device__ float    g_e[(size_t)MAXE * H];
__device__ float    g_eo[(size_t)MAXE * H];
__device__ float    g_l[(size_t)MAXL * H];
__device__ float    g_f[(size_t)MAXF * H];
__device__ __half   g_e16[(size_t)MAXE * H];
__device__ __half   g_l16[(size_t)MAXL * H];
__device__ __half   g_f16[(size_t)MAXF * H];
__device__ __half   g_mh16[(size_t)MAXE * H];
__device__ __half   g_wt16[3][512 * 256];    // transposed weights fp16 [256 n][512 k]
__device__ int      g_cnt[CSRTOT];
__device__ int      g_off[CSRTOT];
__device__ int      g_cur[CSRTOT];
__device__ int      g_col[MAXPAIR];
__device__ int      g_bsum[192];

// ---------- helpers ----------
__device__ __forceinline__ float leaky(float a) { return a >= 0.f ? a : 0.01f * a; }

__device__ __forceinline__ void mma_fp16(float c[4], const unsigned a[4], const unsigned b[2]) {
    asm volatile(
        "mma.sync.aligned.m16n8k16.row.col.f32.f16.f16.f32 "
        "{%0,%1,%2,%3},{%4,%5,%6,%7},{%8,%9},{%0,%1,%2,%3};"
        : "+f"(c[0]), "+f"(c[1]), "+f"(c[2]), "+f"(c[3])
        : "r"(a[0]), "r"(a[1]), "r"(a[2]), "r"(a[3]), "r"(b[0]), "r"(b[1]));
}

__device__ __forceinline__ void cp16(void* s, const void* g, bool valid) {
    unsigned saddr = (unsigned)__cvta_generic_to_shared(s);
    int sz = valid ? 16 : 0;
    asm volatile("cp.async.cg.shared.global [%0], [%1], 16, %2;" :: "r"(saddr), "l"(g), "r"(sz));
}
__device__ __forceinline__ void cp_commit() { asm volatile("cp.async.commit_group;"); }
template<int N> __device__ __forceinline__ void cp_wait() { asm volatile("cp.async.wait_group %0;" :: "n"(N)); }

// ---------- embedding: fp32 out + optional fp16 out ----------
template<int W0, int W1, int W2>
__global__ void embed_kernel(const float* __restrict__ s0,
                             const float* __restrict__ s1,
                             const float* __restrict__ s2,
                             const float* __restrict__ W, const float* __restrict__ bias,
                             float* __restrict__ out, __half* __restrict__ out16, int n) {
    const int RB = 32;
    const int IN = W0 + W1 + W2;
    int row0 = blockIdx.x * RB;
    int tid = threadIdx.x;
    int cg = tid & 63, rg = tid >> 6;
    __shared__ float xs[RB][IN + 1];

    for (int i = tid; i < RB * IN; i += 256) {
        int r = i / IN, k = i % IN;
        int row = row0 + r;
        float v = 0.f;
        if (row < n) {
            if (k < W0)            v = s0[(size_t)row * W0 + k];
            else if (k < W0 + W1)  v = s1[(size_t)row * W1 + (k - W0)];
            else                   v = s2[row];
        }
        xs[r][k] = v;
    }
    __syncthreads();

    float4 b = reinterpret_cast<const float4*>(bias)[cg];
    float4 acc[8];
#pragma unroll
    for (int q = 0; q < 8; q++) acc[q] = b;
#pragma unroll
    for (int k = 0; k < IN; k++) {
        float4 w = reinterpret_cast<const float4*>(W + (size_t)k * H)[cg];
#pragma unroll
        for (int q = 0; q < 8; q++) {
            float xv = xs[rg * 8 + q][k];
            acc[q].x += xv * w.x; acc[q].y += xv * w.y;
            acc[q].z += xv * w.z; acc[q].w += xv * w.w;
        }
    }
#pragma unroll
    for (int q = 0; q < 8; q++) {
        int row = row0 + rg * 8 + q;
        if (row < n) {
            float4 o = make_float4(leaky(acc[q].x), leaky(acc[q].y),
                                   leaky(acc[q].z), leaky(acc[q].w));
            reinterpret_cast<float4*>(out + (size_t)row * H)[cg] = o;
            if (out16) {
                __half2 h0 = __floats2half2_rn(o.x, o.y);
                __half2 h1 = __floats2half2_rn(o.z, o.w);
                __half2* p = reinterpret_cast<__half2*>(out16 + (size_t)row * H) + cg * 2;
                p[0] = h0; p[1] = h1;
            }
        }
    }
}

// ---------- weight transpose: W[512,256] f32 -> Wt16[256,512] f16 ----------
__global__ void transpose_w(const float* __restrict__ W, __half* __restrict__ Wt) {
    __shared__ float t[32][33];
    int bx = blockIdx.x * 32;  // k
    int by = blockIdx.y * 32;  // n
    int tx = threadIdx.x, ty = threadIdx.y;  // 32 x 8
#pragma unroll
    for (int i = 0; i < 4; i++)
        t[ty + i * 8][tx] = W[(size_t)(bx + ty + i * 8) * 256 + by + tx];
    __syncthreads();
#pragma unroll
    for (int i = 0; i < 4; i++)
        Wt[(size_t)(by + ty + i * 8) * 512 + bx + tx] = __float2half_rn(t[tx][ty + i * 8]);
}

// ---------- batched CSR build ----------
__global__ void count_all_kernel(const int* __restrict__ d0, int n0,
                                 const int* __restrict__ d1, int n1,
                                 const int* __restrict__ d2, int n2,
                                 int* __restrict__ cnt) {
    int i = blockIdx.x * blockDim.x + threadIdx.x;
    if (i < n0)                atomicAdd(&cnt[OFF0 + d0[i]], 1);
    else if (i < n0 + n1)      atomicAdd(&cnt[OFF1 + d1[i - n0]], 1);
    else if (i < n0 + n1 + n2) atomicAdd(&cnt[OFF2 + d2[i - n0 - n1]], 1);
}

__global__ void scan_phase1(const int* __restrict__ cnt, int na, int nb_, int nc,
                            int* __restrict__ off, int* __restrict__ bsum) {
    __shared__ int wsum[32];
    int conv = blockIdx.y;
    int n = (conv == 0) ? na : (conv == 1) ? nb_ : nc;
    if (blockIdx.x * 4096 >= n) return;
    int base0 = (conv == 0) ? OFF0 : (conv == 1) ? OFF1 : OFF2;
    const int* c = cnt + base0;
    int* o = off + base0;
    int tid = threadIdx.x, lane = tid & 31, wid = tid >> 5;
    int base = blockIdx.x * 4096 + tid * 4;
    int v0 = (base     < n) ? c[base]     : 0;
    int v1 = (base + 1 < n) ? c[base + 1] : 0;
    int v2 = (base + 2 < n) ? c[base + 2] : 0;
    int v3 = (base + 3 < n) ? c[base + 3] : 0;
    int s = v0 + v1 + v2 + v3;
    int x = s;
#pragma unroll
    for (int d = 1; d < 32; d <<= 1) {
        int y = __shfl_up_sync(~0u, x, d);
        if (lane >= d) x += y;
    }
    if (lane == 31) wsum[wid] = x;
    __syncthreads();
    if (wid == 0) {
        int w = wsum[lane];
#pragma unroll
        for (int d = 1; d < 32; d <<= 1) {
            int y = __shfl_up_sync(~0u, w, d);
            if (lane >= d) w += y;
        }
        wsum[lane] = w;
    }
    __syncthreads();
    int run = x - s + (wid ? wsum[wid - 1] : 0);
    if (base     < n) o[base]     = run; run += v0;
    if (base + 1 < n) o[base + 1] = run; run += v1;
    if (base + 2 < n) o[base + 2] = run; run += v2;
    if (base + 3 < n) o[base + 3] = run;
    if (tid == 0) bsum[conv * 64 + blockIdx.x] = wsum[31];
}

__global__ void scan_phase2(int* __restrict__ bsum, int na, int nb_, int nc,
                            int* __restrict__ off) {
    __shared__ int tmp[64];
    int conv = blockIdx.x;
    int n = (conv == 0) ? na : (conv == 1) ? nb_ : nc;
    int base0 = (conv == 0) ? OFF0 : (conv == 1) ? OFF1 : OFF2;
    int* bs = bsum + conv * 64;
    int nb = (n + 4095) / 4096;
    int tid = threadIdx.x;
    int v = (tid < nb) ? bs[tid] : 0;
    tmp[tid] = v;
    __syncthreads();
    int x = v;
    for (int d = 1; d < 64; d <<= 1) {
        int y = (tid >= d) ? tmp[tid - d] : 0;
        __syncthreads();
        x += y;
        tmp[tid] = x;
        __syncthreads();
    }
    if (tid < nb) bs[tid] = x - v;
    if (tid == 63) off[base0 + n] = x;
}

__global__ void scan_phase3(int* __restrict__ off, const int* __restrict__ bsum,
                            int na, int nb_, int nc, int* __restrict__ cur) {
    int conv = blockIdx.y;
    int n = (conv == 0) ? na : (conv == 1) ? nb_ : nc;
    int i = blockIdx.x * blockDim.x + threadIdx.x;
    if (i >= n) return;
    int base0 = (conv == 0) ? OFF0 : (conv == 1) ? OFF1 : OFF2;
    int o = off[base0 + i] + bsum[conv * 64 + (i >> 12)];
    off[base0 + i] = o;
    cur[base0 + i] = o;
}

__global__ void fill_all_kernel(const int* __restrict__ e0, int n0,
                                const int* __restrict__ e1, int n1,
                                const int* __restrict__ e2, int n2,
                                int* __restrict__ cur, int* __restrict__ col) {
    int i = blockIdx.x * blockDim.x + threadIdx.x;
    const int* idx; int j, np, base0, cbase;
    if (i < n0)                { idx = e0; j = i;           np = n0; base0 = OFF0; cbase = 0; }
    else if (i < n0 + n1)      { idx = e1; j = i - n0;      np = n1; base0 = OFF1; cbase = n0; }
    else if (i < n0 + n1 + n2) { idx = e2; j = i - n0 - n1; np = n2; base0 = OFF2; cbase = n0 + n1; }
    else return;
    int d = idx[j];
    int s = idx[j + np];
    int pos = atomicAdd(&cur[base0 + d], 1);
    col[cbase + pos] = s;
}

// ---------- fused segment-min + (x_dst - min), fp16 output ----------
__global__ void segmin_csr_kernel(const int* __restrict__ off, const int* __restrict__ col,
                                  int n_dst,
                                  const float* __restrict__ xsrc,
                                  const float* __restrict__ xdst,
                                  __half* __restrict__ mh16) {
    int w = (blockIdx.x * blockDim.x + threadIdx.x) >> 5;
    int lane = threadIdx.x & 31;
    if (w >= n_dst) return;
    int beg = off[w], end = off[w + 1];
    const float INF = __int_as_float(0x7f800000);
    float4 m0 = make_float4(INF, INF, INF, INF);
    float4 m1 = m0;
    for (int j = beg; j < end; j++) {
        int s = col[j];
        const float4* r = reinterpret_cast<const float4*>(xsrc + (size_t)s * H);
        float4 v0 = r[lane];
        float4 v1 = r[lane + 32];
        m0.x = fminf(m0.x, v0.x); m0.y = fminf(m0.y, v0.y);
        m0.z = fminf(m0.z, v0.z); m0.w = fminf(m0.w, v0.w);
        m1.x = fminf(m1.x, v1.x); m1.y = fminf(m1.y, v1.y);
        m1.z = fminf(m1.z, v1.z); m1.w = fminf(m1.w, v1.w);
    }
    const float4* xd = reinterpret_cast<const float4*>(xdst + (size_t)w * H);
    float4 d0 = xd[lane], d1 = xd[lane + 32];
    float4 o0, o1;
    if (beg < end) {
        o0 = make_float4(d0.x - m0.x, d0.y - m0.y, d0.z - m0.z, d0.w - m0.w);
        o1 = make_float4(d1.x - m1.x, d1.y - m1.y, d1.z - m1.z, d1.w - m1.w);
    } else {
        o0 = make_float4(0.f, 0.f, 0.f, 0.f);
        o1 = o0;
    }
    __half2* mo = reinterpret_cast<__half2*>(mh16 + (size_t)w * H);
    mo[lane * 2]          = __floats2half2_rn(o0.x, o0.y);
    mo[lane * 2 + 1]      = __floats2half2_rn(o0.z, o0.w);
    mo[64 + lane * 2]     = __floats2half2_rn(o1.x, o1.y);
    mo[64 + lane * 2 + 1] = __floats2half2_rn(o1.z, o1.w);
}

// ---------- fp16 tensor-core conv GEMM: out = x + leaky([x16 | mh16] @ Wt16^T + b) ----------
// block tile 128x128x32, 8 warps (2x4), warp tile 64x32, m16n8k16
#define BM 128
#define BN 128
#define BK 32
#define RSTR 20                 // row stride in 32-bit words (16 used + 4 pad)
#define TSZ (128 * RSTR)        // one tile in words

__global__ __launch_bounds__(256) void conv_gemm_fp16(const float* __restrict__ x,
                                                      const __half* __restrict__ x16,
                                                      const __half* __restrict__ mh16,
                                                      const __half* __restrict__ Wt16,
                                                      const float* __restrict__ bias,
                                                      float* __restrict__ out, int M) {
    __shared__ unsigned As[2][TSZ];
    __shared__ unsigned Bs[2][TSZ];
    int tid = threadIdx.x;
    int warp = tid >> 5, lane = tid & 31;
    int g = lane >> 2, t = lane & 3;
    int wr = warp >> 2, wc = warp & 3;
    int m_w = wr * 64, n_w = wc * 32;
    int bm = blockIdx.x * BM, bn = blockIdx.y * BN;

    int prow = tid >> 2;            // 0..63
    int pc = (tid & 3);             // chunk 0..3 (16B = 4 words = 8 halves)

    float c[4][4][4];
#pragma unroll
    for (int i = 0; i < 4; i++)
#pragma unroll
        for (int j = 0; j < 4; j++)
#pragma unroll
            for (int q = 0; q < 4; q++) c[i][j][q] = 0.f;

    auto prefetch = [&](int k0, int buf) {
        const __half* Ab = (k0 < 256) ? x16 : mh16;
        int kk = k0 & 255;
#pragma unroll
        for (int r = 0; r < 2; r++) {
            int row = prow + r * 64;
            bool v = (bm + row) < M;
            const __half* gp = Ab + (size_t)(v ? bm + row : 0) * H + kk + pc * 8;
            cp16(&As[buf][row * RSTR + pc * 4], gp, v);
        }
#pragma unroll
        for (int r = 0; r < 2; r++) {
            int row = prow + r * 64;
            cp16(&Bs[buf][row * RSTR + pc * 4],
                 Wt16 + (size_t)(bn + row) * 512 + k0 + pc * 8, true);
        }
        cp_commit();
    };

    prefetch(0, 0);

    for (int it = 0; it < 16; it++) {
        int buf = it & 1;
        if (it < 15) {
            prefetch((it + 1) * BK, buf ^ 1);
            cp_wait<1>();
        } else {
            cp_wait<0>();
        }
        __syncthreads();

        const unsigned* Asb = As[buf];
        const unsigned* Bsb = Bs[buf];
#pragma unroll
        for (int ks = 0; ks < 2; ks++) {
            int kb2 = ks * 8;
            unsigned a[4][4], b[4][2];
#pragma unroll
            for (int i = 0; i < 4; i++) {
                int mb = m_w + i * 16;
                a[i][0] = Asb[(mb + g) * RSTR + kb2 + t];
                a[i][1] = Asb[(mb + g + 8) * RSTR + kb2 + t];
                a[i][2] = Asb[(mb + g) * RSTR + kb2 + 4 + t];
                a[i][3] = Asb[(mb + g + 8) * RSTR + kb2 + 4 + t];
            }
#pragma unroll
            for (int j = 0; j < 4; j++) {
                int nb = n_w + j * 8;
                b[j][0] = Bsb[(nb + g) * RSTR + kb2 + t];
                b[j][1] = Bsb[(nb + g) * RSTR + kb2 + 4 + t];
            }
#pragma unroll
            for (int i = 0; i < 4; i++)
#pragma unroll
                for (int j = 0; j < 4; j++) mma_fp16(c[i][j], a[i], b[j]);
        }
        __syncthreads();
    }

    // epilogue: out = x + leaky(c + bias)
#pragma unroll
    for (int i = 0; i < 4; i++) {
        int r0 = bm + m_w + i * 16 + g;
        int r1 = r0 + 8;
#pragma unroll
        for (int j = 0; j < 4; j++) {
            int col = bn + n_w + j * 8 + t * 2;
            float b0 = bias[col], b1 = bias[col + 1];
            if (r0 < M) {
                size_t o = (size_t)r0 * H + col;
                out[o]     = x[o]     + leaky(c[i][j][0] + b0);
                out[o + 1] = x[o + 1] + leaky(c[i][j][1] + b1);
            }
            if (r1 < M) {
                size_t o = (size_t)r1 * H + col;
                out[o]     = x[o]     + leaky(c[i][j][2] + b0);
                out[o + 1] = x[o + 1] + leaky(c[i][j][3] + b1);
            }
        }
    }
}

// ---------- launch ----------
static inline int cdiv(int a, int b) { return (a + b - 1) / b; }

extern "C" void kernel_launch(void* const* d_in, const int* in_sizes, int n_in,
                              void* d_out, int out_size) {
    const float* vp  = (const float*)d_in[0];
    const float* ec  = (const float*)d_in[1];
    const float* ecp = (const float*)d_in[2];
    const float* ecf = (const float*)d_in[3];
    const float* lt  = (const float*)d_in[4];
    const float* fs  = (const float*)d_in[5];
    const float* fsp = (const float*)d_in[6];
    const float* fsf = (const float*)d_in[7];
    const int* ev = (const int*)d_in[8];
    const int* le = (const int*)d_in[9];
    const int* fl = (const int*)d_in[10];
    const float* Wv = (const float*)d_in[11]; const float* bv = (const float*)d_in[12];
    const float* We = (const float*)d_in[13]; const float* be = (const float*)d_in[14];
    const float* Wl = (const float*)d_in[15]; const float* bl = (const float*)d_in[16];
    const float* Wf = (const float*)d_in[17]; const float* bf = (const float*)d_in[18];
    const float* Wve = (const float*)d_in[19]; const float* bve = (const float*)d_in[20];
    const float* Wel = (const float*)d_in[21]; const float* bel = (const float*)d_in[22];
    const float* Wlf = (const float*)d_in[23]; const float* blf = (const float*)d_in[24];

    int NVn = in_sizes[0] / 3;
    int NEn = in_sizes[1] / 8;
    int NLn = in_sizes[4] / 10;
    int NFn = in_sizes[5] / 12;
    int nEV = in_sizes[8] / 2;
    int nLE = in_sizes[9] / 2;
    int nFL = in_sizes[10] / 2;

    float *pv, *pe, *peo, *pl, *pf;
    __half *pe16, *pl16, *pf16, *pmh16, *pwt16;
    int *pcnt, *poff, *pcur, *pcol, *pbsum;
    cudaGetSymbolAddress((void**)&pv,    g_v);
    cudaGetSymbolAddress((void**)&pe,    g_e);
    cudaGetSymbolAddress((void**)&peo,   g_eo);
    cudaGetSymbolAddress((void**)&pl,    g_l);
    cudaGetSymbolAddress((void**)&pf,    g_f);
    cudaGetSymbolAddress((void**)&pe16,  g_e16);
    cudaGetSymbolAddress((void**)&pl16,  g_l16);
    cudaGetSymbolAddress((void**)&pf16,  g_f16);
    cudaGetSymbolAddress((void**)&pmh16, g_mh16);
    cudaGetSymbolAddress((void**)&pwt16, g_wt16);
    cudaGetSymbolAddress((void**)&pcnt,  g_cnt);
    cudaGetSymbolAddress((void**)&poff,  g_off);
    cudaGetSymbolAddress((void**)&pcur,  g_cur);
    cudaGetSymbolAddress((void**)&pcol,  g_col);
    cudaGetSymbolAddress((void**)&pbsum, g_bsum);

    int nPairTot = nEV + nLE + nFL;
    int nmax = NEn;

    // weight transposes (fp32 -> fp16 [n][k])
    {
        dim3 g(16, 8), b(32, 8);
        transpose_w<<<g, b>>>(Wve, pwt16);
        transpose_w<<<g, b>>>(Wel, pwt16 + 512 * 256);
        transpose_w<<<g, b>>>(Wlf, pwt16 + 2 * 512 * 256);
    }

    // batched CSR build
    cudaMemsetAsync(pcnt, 0, (size_t)CSRTOT * sizeof(int));
    count_all_kernel<<<cdiv(nPairTot, 256), 256>>>(ev, nEV, le, nLE, fl, nFL, pcnt);
    {
        dim3 g1(cdiv(nmax, 4096), 3);
        scan_phase1<<<g1, 1024>>>(pcnt, NEn, NLn, NFn, poff, pbsum);
        scan_phase2<<<3, 64>>>(pbsum, NEn, NLn, NFn, poff);
        dim3 g3(cdiv(nmax, 256), 3);
        scan_phase3<<<g3, 256>>>(poff, pbsum, NEn, NLn, NFn, pcur);
    }
    fill_all_kernel<<<cdiv(nPairTot, 256), 256>>>(ev, nEV, le, nLE, fl, nFL, pcur, pcol);

    // embeddings (v: fp32 only; e/l/f: fp32 + fp16)
    embed_kernel<3, 0, 0><<<cdiv(NVn, 32), 256>>>(vp, nullptr, nullptr, Wv, bv, pv, nullptr, NVn);
    embed_kernel<8, 6, 1><<<cdiv(NEn, 32), 256>>>(ec, ecp, ecf, We, be, pe, pe16, NEn);
    embed_kernel<10, 0, 0><<<cdiv(NLn, 32), 256>>>(lt, nullptr, nullptr, Wl, bl, pl, pl16, NLn);
    embed_kernel<12, 4, 1><<<cdiv(NFn, 32), 256>>>(fs, fsp, fsf, Wf, bf, pf, pf16, NFn);

    // conv 1: vertices -> edges
    segmin_csr_kernel<<<cdiv(NEn * 32, 256), 256>>>(poff + OFF0, pcol, NEn, pv, pe, pmh16);
    {
        dim3 g(cdiv(NEn, BM), 2);
        conv_gemm_fp16<<<g, 256>>>(pe, pe16, pmh16, pwt16, bve, peo, NEn);
    }
    // conv 2: edges -> loops (output reuses g_v)
    segmin_csr_kernel<<<cdiv(NLn * 32, 256), 256>>>(poff + OFF1, pcol + nEV, NLn, peo, pl, pmh16);
    {
        dim3 g(cdiv(NLn, BM), 2);
        conv_gemm_fp16<<<g, 256>>>(pl, pl16, pmh16, pwt16 + 512 * 256, bel, pv, NLn);
    }
    // conv 3: loops -> faces (output = d_out)
    segmin_csr_kernel<<<cdiv(NFn * 32, 256), 256>>>(poff + OFF2, pcol + nEV + nLE, NFn, pv, pf, pmh16);
    {
        dim3 g(cdiv(NFn, BM), 2);
        conv_gemm_fp16<<<g, 256>>>(pf, pf16, pmh16, pwt16 + 2 * 512 * 256, blf, (float*)d_out, NFn);
    }
}

// round 8
// speedup vs baseline: 1.1612x; 1.0091x over previous
#include <cuda_runtime.h>
#include <cuda_fp16.h>
#include <cstdint>

#define H 256

#define MAXV 100000
#define MAXE 150000
#define MAXL 80000
#define MAXF 60000
#define MAXPAIR 800000

#define OFF0 0
#define OFF1 (MAXE + 1)
#define OFF2 (MAXE + 1 + MAXL + 1)
#define CSRTOT (MAXE + MAXL + MAXF + 3)

// scratch
__device__ float    g_v[(size_t)MAXV * H];
__device__ float    g_e[(size_t)MAXE * H];
__device__ float    g_eo[(size_t)MAXE * H];
__device__ float    g_l[(size_t)MAXL * H];
__device__ float    g_f[(size_t)MAXF * H];
__device__ __half   g_v16[(size_t)MAXV * H];   // vertex embed fp16; reused as conv2-output fp16
__device__ __half   g_e16[(size_t)MAXE * H];
__device__ __half   g_eo16[(size_t)MAXE * H];  // conv1 output fp16
__device__ __half   g_l16[(size_t)MAXL * H];
__device__ __half   g_f16[(size_t)MAXF * H];
__device__ __half   g_mh16[(size_t)MAXE * H];
__device__ __half   g_wt16[3][512 * 256];      // transposed weights fp16 [256 n][512 k]
__device__ int      g_cnt[CSRTOT];
__device__ int      g_off[CSRTOT];
__device__ int      g_cur[CSRTOT];
__device__ int      g_col[MAXPAIR];
__device__ int      g_bsum[192];

// ---------- helpers ----------
__device__ __forceinline__ float leaky(float a) { return a >= 0.f ? a : 0.01f * a; }

__device__ __forceinline__ void mma_fp16(float c[4], const unsigned a[4], const unsigned b[2]) {
    asm volatile(
        "mma.sync.aligned.m16n8k16.row.col.f32.f16.f16.f32 "
        "{%0,%1,%2,%3},{%4,%5,%6,%7},{%8,%9},{%0,%1,%2,%3};"
        : "+f"(c[0]), "+f"(c[1]), "+f"(c[2]), "+f"(c[3])
        : "r"(a[0]), "r"(a[1]), "r"(a[2]), "r"(a[3]), "r"(b[0]), "r"(b[1]));
}

__device__ __forceinline__ void cp16(void* s, const void* g, bool valid) {
    unsigned saddr = (unsigned)__cvta_generic_to_shared(s);
    int sz = valid ? 16 : 0;
    asm volatile("cp.async.cg.shared.global [%0], [%1], 16, %2;" :: "r"(saddr), "l"(g), "r"(sz));
}
__device__ __forceinline__ void cp_commit() { asm volatile("cp.async.commit_group;"); }
template<int N> __device__ __forceinline__ void cp_wait() { asm volatile("cp.async.wait_group %0;" :: "n"(N)); }

// ---------- embedding: fp32 out + optional fp16 out ----------
template<int W0, int W1, int W2>
__global__ void embed_kernel(const float* __restrict__ s0,
                             const float* __restrict__ s1,
                             const float* __restrict__ s2,
                             const float* __restrict__ W, const float* __restrict__ bias,
                             float* __restrict__ out, __half* __restrict__ out16, int n) {
    const int RB = 32;
    const int IN = W0 + W1 + W2;
    int row0 = blockIdx.x * RB;
    int tid = threadIdx.x;
    int cg = tid & 63, rg = tid >> 6;
    __shared__ float xs[RB][IN + 1];

    for (int i = tid; i < RB * IN; i += 256) {
        int r = i / IN, k = i % IN;
        int row = row0 + r;
        float v = 0.f;
        if (row < n) {
            if (k < W0)            v = s0[(size_t)row * W0 + k];
            else if (k < W0 + W1)  v = s1[(size_t)row * W1 + (k - W0)];
            else                   v = s2[row];
        }
        xs[r][k] = v;
    }
    __syncthreads();

    float4 b = reinterpret_cast<const float4*>(bias)[cg];
    float4 acc[8];
#pragma unroll
    for (int q = 0; q < 8; q++) acc[q] = b;
#pragma unroll
    for (int k = 0; k < IN; k++) {
        float4 w = reinterpret_cast<const float4*>(W + (size_t)k * H)[cg];
#pragma unroll
        for (int q = 0; q < 8; q++) {
            float xv = xs[rg * 8 + q][k];
            acc[q].x += xv * w.x; acc[q].y += xv * w.y;
            acc[q].z += xv * w.z; acc[q].w += xv * w.w;
        }
    }
#pragma unroll
    for (int q = 0; q < 8; q++) {
        int row = row0 + rg * 8 + q;
        if (row < n) {
            float4 o = make_float4(leaky(acc[q].x), leaky(acc[q].y),
                                   leaky(acc[q].z), leaky(acc[q].w));
            reinterpret_cast<float4*>(out + (size_t)row * H)[cg] = o;
            if (out16) {
                __half2 h0 = __floats2half2_rn(o.x, o.y);
                __half2 h1 = __floats2half2_rn(o.z, o.w);
                __half2* p = reinterpret_cast<__half2*>(out16 + (size_t)row * H) + cg * 2;
                p[0] = h0; p[1] = h1;
            }
        }
    }
}

// ---------- weight transpose: W[512,256] f32 -> Wt16[256,512] f16 ----------
__global__ void transpose_w(const float* __restrict__ W, __half* __restrict__ Wt) {
    __shared__ float t[32][33];
    int bx = blockIdx.x * 32;  // k
    int by = blockIdx.y * 32;  // n
    int tx = threadIdx.x, ty = threadIdx.y;  // 32 x 8
#pragma unroll
    for (int i = 0; i < 4; i++)
        t[ty + i * 8][tx] = W[(size_t)(bx + ty + i * 8) * 256 + by + tx];
    __syncthreads();
#pragma unroll
    for (int i = 0; i < 4; i++)
        Wt[(size_t)(by + ty + i * 8) * 512 + bx + tx] = __float2half_rn(t[tx][ty + i * 8]);
}

// ---------- batched CSR build ----------
__global__ void count_all_kernel(const int* __restrict__ d0, int n0,
                                 const int* __restrict__ d1, int n1,
                                 const int* __restrict__ d2, int n2,
                                 int* __restrict__ cnt) {
    int i = blockIdx.x * blockDim.x + threadIdx.x;
    if (i < n0)                atomicAdd(&cnt[OFF0 + d0[i]], 1);
    else if (i < n0 + n1)      atomicAdd(&cnt[OFF1 + d1[i - n0]], 1);
    else if (i < n0 + n1 + n2) atomicAdd(&cnt[OFF2 + d2[i - n0 - n1]], 1);
}

__global__ void scan_phase1(const int* __restrict__ cnt, int na, int nb_, int nc,
                            int* __restrict__ off, int* __restrict__ bsum) {
    __shared__ int wsum[32];
    int conv = blockIdx.y;
    int n = (conv == 0) ? na : (conv == 1) ? nb_ : nc;
    if (blockIdx.x * 4096 >= n) return;
    int base0 = (conv == 0) ? OFF0 : (conv == 1) ? OFF1 : OFF2;
    const int* c = cnt + base0;
    int* o = off + base0;
    int tid = threadIdx.x, lane = tid & 31, wid = tid >> 5;
    int base = blockIdx.x * 4096 + tid * 4;
    int v0 = (base     < n) ? c[base]     : 0;
    int v1 = (base + 1 < n) ? c[base + 1] : 0;
    int v2 = (base + 2 < n) ? c[base + 2] : 0;
    int v3 = (base + 3 < n) ? c[base + 3] : 0;
    int s = v0 + v1 + v2 + v3;
    int x = s;
#pragma unroll
    for (int d = 1; d < 32; d <<= 1) {
        int y = __shfl_up_sync(~0u, x, d);
        if (lane >= d) x += y;
    }
    if (lane == 31) wsum[wid] = x;
    __syncthreads();
    if (wid == 0) {
        int w = wsum[lane];
#pragma unroll
        for (int d = 1; d < 32; d <<= 1) {
            int y = __shfl_up_sync(~0u, w, d);
            if (lane >= d) w += y;
        }
        wsum[lane] = w;
    }
    __syncthreads();
    int run = x - s + (wid ? wsum[wid - 1] : 0);
    if (base     < n) o[base]     = run; run += v0;
    if (base + 1 < n) o[base + 1] = run; run += v1;
    if (base + 2 < n) o[base + 2] = run; run += v2;
    if (base + 3 < n) o[base + 3] = run;
    if (tid == 0) bsum[conv * 64 + blockIdx.x] = wsum[31];
}

__global__ void scan_phase2(int* __restrict__ bsum, int na, int nb_, int nc,
                            int* __restrict__ off) {
    __shared__ int tmp[64];
    int conv = blockIdx.x;
    int n = (conv == 0) ? na : (conv == 1) ? nb_ : nc;
    int base0 = (conv == 0) ? OFF0 : (conv == 1) ? OFF1 : OFF2;
    int* bs = bsum + conv * 64;
    int nb = (n + 4095) / 4096;
    int tid = threadIdx.x;
    int v = (tid < nb) ? bs[tid] : 0;
    tmp[tid] = v;
    __syncthreads();
    int x = v;
    for (int d = 1; d < 64; d <<= 1) {
        int y = (tid >= d) ? tmp[tid - d] : 0;
        __syncthreads();
        x += y;
        tmp[tid] = x;
        __syncthreads();
    }
    if (tid < nb) bs[tid] = x - v;
    if (tid == 63) off[base0 + n] = x;
}

__global__ void scan_phase3(int* __restrict__ off, const int* __restrict__ bsum,
                            int na, int nb_, int nc, int* __restrict__ cur) {
    int conv = blockIdx.y;
    int n = (conv == 0) ? na : (conv == 1) ? nb_ : nc;
    int i = blockIdx.x * blockDim.x + threadIdx.x;
    if (i >= n) return;
    int base0 = (conv == 0) ? OFF0 : (conv == 1) ? OFF1 : OFF2;
    int o = off[base0 + i] + bsum[conv * 64 + (i >> 12)];
    off[base0 + i] = o;
    cur[base0 + i] = o;
}

__global__ void fill_all_kernel(const int* __restrict__ e0, int n0,
                                const int* __restrict__ e1, int n1,
                                const int* __restrict__ e2, int n2,
                                int* __restrict__ cur, int* __restrict__ col) {
    int i = blockIdx.x * blockDim.x + threadIdx.x;
    const int* idx; int j, np, base0, cbase;
    if (i < n0)                { idx = e0; j = i;           np = n0; base0 = OFF0; cbase = 0; }
    else if (i < n0 + n1)      { idx = e1; j = i - n0;      np = n1; base0 = OFF1; cbase = n0; }
    else if (i < n0 + n1 + n2) { idx = e2; j = i - n0 - n1; np = n2; base0 = OFF2; cbase = n0 + n1; }
    else return;
    int d = idx[j];
    int s = idx[j + np];
    int pos = atomicAdd(&cur[base0 + d], 1);
    col[cbase + pos] = s;
}

// ---------- fused segment-min (fp16 gather) + (x_dst - min) -> fp16 ----------
__global__ void segmin_csr_kernel(const int* __restrict__ off, const int* __restrict__ col,
                                  int n_dst,
                                  const __half* __restrict__ xsrc16,
                                  const float* __restrict__ xdst,
                                  __half* __restrict__ mh16) {
    int w = (blockIdx.x * blockDim.x + threadIdx.x) >> 5;
    int lane = threadIdx.x & 31;
    if (w >= n_dst) return;
    int beg = off[w], end = off[w + 1];
    __half2 m[4];
    const __half2 inf2 = __halves2half2(__ushort_as_half(0x7C00), __ushort_as_half(0x7C00));
#pragma unroll
    for (int q = 0; q < 4; q++) m[q] = inf2;
    for (int j = beg; j < end; j++) {
        int s = col[j];
        uint4 v = reinterpret_cast<const uint4*>(xsrc16 + (size_t)s * H)[lane];
        const __half2* h = reinterpret_cast<const __half2*>(&v);
        m[0] = __hmin2(m[0], h[0]);
        m[1] = __hmin2(m[1], h[1]);
        m[2] = __hmin2(m[2], h[2]);
        m[3] = __hmin2(m[3], h[3]);
    }
    // this lane's 8 columns: lane*8 .. lane*8+7
    const float4* xd = reinterpret_cast<const float4*>(xdst + (size_t)w * H) + lane * 2;
    float4 d0 = xd[0], d1 = xd[1];
    uint4 outv;
    __half2* oh = reinterpret_cast<__half2*>(&outv);
    if (beg < end) {
        float2 f0 = __half22float2(m[0]), f1 = __half22float2(m[1]);
        float2 f2 = __half22float2(m[2]), f3 = __half22float2(m[3]);
        oh[0] = __floats2half2_rn(d0.x - f0.x, d0.y - f0.y);
        oh[1] = __floats2half2_rn(d0.z - f1.x, d0.w - f1.y);
        oh[2] = __floats2half2_rn(d1.x - f2.x, d1.y - f2.y);
        oh[3] = __floats2half2_rn(d1.z - f3.x, d1.w - f3.y);
    } else {
        outv = make_uint4(0, 0, 0, 0);
    }
    reinterpret_cast<uint4*>(mh16 + (size_t)w * H)[lane] = outv;
}

// ---------- fp16 tensor-core conv GEMM: 128x256 block tile ----------
// 8 warps (2x4), warp tile 64x64, m16n8k16, double-buffered cp.async
#define BM 128
#define BK 32
#define RSTR 20                  // row stride in 32-bit words (16 used + 4 pad)
#define A_WORDS (128 * RSTR)     // 2560
#define B_WORDS (256 * RSTR)     // 5120
#define GEMM_SMEM ((2 * A_WORDS + 2 * B_WORDS) * 4)   // 61440 B

__global__ __launch_bounds__(256, 1) void conv_gemm_fp16(const float* __restrict__ x,
                                                         const __half* __restrict__ x16,
                                                         const __half* __restrict__ mh16,
                                                         const __half* __restrict__ Wt16,
                                                         const float* __restrict__ bias,
                                                         float* __restrict__ out,
                                                         __half* __restrict__ out16, int M) {
    extern __shared__ unsigned sm[];
    unsigned* As = sm;                   // 2 x A_WORDS
    unsigned* Bs = sm + 2 * A_WORDS;     // 2 x B_WORDS
    int tid = threadIdx.x;
    int warp = tid >> 5, lane = tid & 31;
    int g = lane >> 2, t = lane & 3;
    int wr = warp >> 2, wc = warp & 3;
    int m_w = wr * 64, n_w = wc * 64;
    int bm = blockIdx.x * BM;

    int prow = tid >> 2;            // 0..63
    int pc = tid & 3;               // 16B chunk within row

    float c[4][8][4];
#pragma unroll
    for (int i = 0; i < 4; i++)
#pragma unroll
        for (int j = 0; j < 8; j++)
#pragma unroll
            for (int q = 0; q < 4; q++) c[i][j][q] = 0.f;

    auto prefetch = [&](int k0, int buf) {
        const __half* Ab = (k0 < 256) ? x16 : mh16;
        int kk = k0 & 255;
        unsigned* Ad = As + buf * A_WORDS;
        unsigned* Bd = Bs + buf * B_WORDS;
#pragma unroll
        for (int r = 0; r < 2; r++) {
            int row = prow + r * 64;
            bool v = (bm + row) < M;
            const __half* gp = Ab + (size_t)(v ? bm + row : 0) * H + kk + pc * 8;
            cp16(Ad + row * RSTR + pc * 4, gp, v);
        }
#pragma unroll
        for (int r = 0; r < 4; r++) {
            int row = prow + r * 64;
            cp16(Bd + row * RSTR + pc * 4,
                 Wt16 + (size_t)row * 512 + k0 + pc * 8, true);
        }
        cp_commit();
    };

    prefetch(0, 0);

    for (int it = 0; it < 16; it++) {
        int buf = it & 1;
        if (it < 15) {
            prefetch((it + 1) * BK, buf ^ 1);
            cp_wait<1>();
        } else {
            cp_wait<0>();
        }
        __syncthreads();

        const unsigned* Asb = As + buf * A_WORDS;
        const unsigned* Bsb = Bs + buf * B_WORDS;
#pragma unroll
        for (int ks = 0; ks < 2; ks++) {
            int kb2 = ks * 8;
            unsigned a[4][4], b[8][2];
#pragma unroll
            for (int i = 0; i < 4; i++) {
                int mb = m_w + i * 16;
                a[i][0] = Asb[(mb + g) * RSTR + kb2 + t];
                a[i][1] = Asb[(mb + g + 8) * RSTR + kb2 + t];
                a[i][2] = Asb[(mb + g) * RSTR + kb2 + 4 + t];
                a[i][3] = Asb[(mb + g + 8) * RSTR + kb2 + 4 + t];
            }
#pragma unroll
            for (int j = 0; j < 8; j++) {
                int nb = n_w + j * 8;
                b[j][0] = Bsb[(nb + g) * RSTR + kb2 + t];
                b[j][1] = Bsb[(nb + g) * RSTR + kb2 + 4 + t];
            }
#pragma unroll
            for (int i = 0; i < 4; i++)
#pragma unroll
                for (int j = 0; j < 8; j++) mma_fp16(c[i][j], a[i], b[j]);
        }
        __syncthreads();
    }

    // epilogue: out = x + leaky(c + bias); optional fp16 copy
#pragma unroll
    for (int i = 0; i < 4; i++) {
        int r0 = bm + m_w + i * 16 + g;
        int r1 = r0 + 8;
#pragma unroll
        for (int j = 0; j < 8; j++) {
            int col = n_w + j * 8 + t * 2;
            float b0 = bias[col], b1 = bias[col + 1];
            if (r0 < M) {
                size_t o = (size_t)r0 * H + col;
                float v0 = x[o]     + leaky(c[i][j][0] + b0);
                float v1 = x[o + 1] + leaky(c[i][j][1] + b1);
                out[o] = v0; out[o + 1] = v1;
                if (out16)
                    *reinterpret_cast<__half2*>(out16 + o) = __floats2half2_rn(v0, v1);
            }
            if (r1 < M) {
                size_t o = (size_t)r1 * H + col;
                float v0 = x[o]     + leaky(c[i][j][2] + b0);
                float v1 = x[o + 1] + leaky(c[i][j][3] + b1);
                out[o] = v0; out[o + 1] = v1;
                if (out16)
                    *reinterpret_cast<__half2*>(out16 + o) = __floats2half2_rn(v0, v1);
            }
        }
    }
}

// ---------- launch ----------
static inline int cdiv(int a, int b) { return (a + b - 1) / b; }

extern "C" void kernel_launch(void* const* d_in, const int* in_sizes, int n_in,
                              void* d_out, int out_size) {
    const float* vp  = (const float*)d_in[0];
    const float* ec  = (const float*)d_in[1];
    const float* ecp = (const float*)d_in[2];
    const float* ecf = (const float*)d_in[3];
    const float* lt  = (const float*)d_in[4];
    const float* fs  = (const float*)d_in[5];
    const float* fsp = (const float*)d_in[6];
    const float* fsf = (const float*)d_in[7];
    const int* ev = (const int*)d_in[8];
    const int* le = (const int*)d_in[9];
    const int* fl = (const int*)d_in[10];
    const float* Wv = (const float*)d_in[11]; const float* bv = (const float*)d_in[12];
    const float* We = (const float*)d_in[13]; const float* be = (const float*)d_in[14];
    const float* Wl = (const float*)d_in[15]; const float* bl = (const float*)d_in[16];
    const float* Wf = (const float*)d_in[17]; const float* bf = (const float*)d_in[18];
    const float* Wve = (const float*)d_in[19]; const float* bve = (const float*)d_in[20];
    const float* Wel = (const float*)d_in[21]; const float* bel = (const float*)d_in[22];
    const float* Wlf = (const float*)d_in[23]; const float* blf = (const float*)d_in[24];

    int NVn = in_sizes[0] / 3;
    int NEn = in_sizes[1] / 8;
    int NLn = in_sizes[4] / 10;
    int NFn = in_sizes[5] / 12;
    int nEV = in_sizes[8] / 2;
    int nLE = in_sizes[9] / 2;
    int nFL = in_sizes[10] / 2;

    float *pv, *pe, *peo, *pl, *pf;
    __half *pv16, *pe16, *peo16, *pl16, *pf16, *pmh16, *pwt16;
    int *pcnt, *poff, *pcur, *pcol, *pbsum;
    cudaGetSymbolAddress((void**)&pv,    g_v);
    cudaGetSymbolAddress((void**)&pe,    g_e);
    cudaGetSymbolAddress((void**)&peo,   g_eo);
    cudaGetSymbolAddress((void**)&pl,    g_l);
    cudaGetSymbolAddress((void**)&pf,    g_f);
    cudaGetSymbolAddress((void**)&pv16,  g_v16);
    cudaGetSymbolAddress((void**)&pe16,  g_e16);
    cudaGetSymbolAddress((void**)&peo16, g_eo16);
    cudaGetSymbolAddress((void**)&pl16,  g_l16);
    cudaGetSymbolAddress((void**)&pf16,  g_f16);
    cudaGetSymbolAddress((void**)&pmh16, g_mh16);
    cudaGetSymbolAddress((void**)&pwt16, g_wt16);
    cudaGetSymbolAddress((void**)&pcnt,  g_cnt);
    cudaGetSymbolAddress((void**)&poff,  g_off);
    cudaGetSymbolAddress((void**)&pcur,  g_cur);
    cudaGetSymbolAddress((void**)&pcol,  g_col);
    cudaGetSymbolAddress((void**)&pbsum, g_bsum);

    cudaFuncSetAttribute(conv_gemm_fp16, cudaFuncAttributeMaxDynamicSharedMemorySize, GEMM_SMEM);

    int nPairTot = nEV + nLE + nFL;
    int nmax = NEn;

    // weight transposes (fp32 -> fp16 [n][k])
    {
        dim3 g(16, 8), b(32, 8);
        transpose_w<<<g, b>>>(Wve, pwt16);
        transpose_w<<<g, b>>>(Wel, pwt16 + 512 * 256);
        transpose_w<<<g, b>>>(Wlf, pwt16 + 2 * 512 * 256);
    }

    // batched CSR build
    cudaMemsetAsync(pcnt, 0, (size_t)CSRTOT * sizeof(int));
    count_all_kernel<<<cdiv(nPairTot, 256), 256>>>(ev, nEV, le, nLE, fl, nFL, pcnt);
    {
        dim3 g1(cdiv(nmax, 4096), 3);
        scan_phase1<<<g1, 1024>>>(pcnt, NEn, NLn, NFn, poff, pbsum);
        scan_phase2<<<3, 64>>>(pbsum, NEn, NLn, NFn, poff);
        dim3 g3(cdiv(nmax, 256), 3);
        scan_phase3<<<g3, 256>>>(poff, pbsum, NEn, NLn, NFn, pcur);
    }
    fill_all_kernel<<<cdiv(nPairTot, 256), 256>>>(ev, nEV, le, nLE, fl, nFL, pcur, pcol);

    // embeddings (all write fp16 copies; vertex fp16 feeds conv1 gather)
    embed_kernel<3, 0, 0><<<cdiv(NVn, 32), 256>>>(vp, nullptr, nullptr, Wv, bv, pv, pv16, NVn);
    embed_kernel<8, 6, 1><<<cdiv(NEn, 32), 256>>>(ec, ecp, ecf, We, be, pe, pe16, NEn);
    embed_kernel<10, 0, 0><<<cdiv(NLn, 32), 256>>>(lt, nullptr, nullptr, Wl, bl, pl, pl16, NLn);
    embed_kernel<12, 4, 1><<<cdiv(NFn, 32), 256>>>(fs, fsp, fsf, Wf, bf, pf, pf16, NFn);

    // conv 1: vertices -> edges   (emit fp16 output for conv2 gather)
    segmin_csr_kernel<<<cdiv(NEn * 32, 256), 256>>>(poff + OFF0, pcol, NEn, pv16, pe, pmh16);
    conv_gemm_fp16<<<cdiv(NEn, BM), 256, GEMM_SMEM>>>(pe, pe16, pmh16, pwt16, bve, peo, peo16, NEn);

    // conv 2: edges -> loops (fp32 out reuses g_v, fp16 out reuses g_v16)
    segmin_csr_kernel<<<cdiv(NLn * 32, 256), 256>>>(poff + OFF1, pcol + nEV, NLn, peo16, pl, pmh16);
    conv_gemm_fp16<<<cdiv(NLn, BM), 256, GEMM_SMEM>>>(pl, pl16, pmh16, pwt16 + 512 * 256, bel, pv, pv16, NLn);

    // conv 3: loops -> faces (output = d_out, no fp16 copy needed)
    segmin_csr_kernel<<<cdiv(NFn * 32, 256), 256>>>(poff + OFF2, pcol + nEV + nLE, NFn, pv16, pf, pmh16);
    conv_gemm_fp16<<<cdiv(NFn, BM), 256, GEMM_SMEM>>>(pf, pf16, pmh16, pwt16 + 2 * 512 * 256, blf, (float*)d_out, nullptr, NFn);
}

// round 9
// speedup vs baseline: 1.4014x; 1.2068x over previous
#include <cuda_runtime.h>
#include <cuda_fp16.h>
#include <cstdint>

#define H 256

#define MAXV 100000
#define MAXE 150000
#define MAXL 80000
#define MAXF 60000
#define MAXPAIR 800000

#define OFF0 0
#define OFF1 (MAXE + 1)
#define OFF2 (MAXE + 1 + MAXL + 1)
#define CSRTOT (MAXE + MAXL + MAXF + 3)

// scratch (fp16 activations only)
__device__ __half   g_v16[(size_t)MAXV * H];   // vertex embed; reused as conv2-output
__device__ __half   g_e16[(size_t)MAXE * H];
__device__ __half   g_eo16[(size_t)MAXE * H];  // conv1 output
__device__ __half   g_l16[(size_t)MAXL * H];
__device__ __half   g_f16[(size_t)MAXF * H];
__device__ __half   g_mh16[(size_t)MAXE * H];
__device__ __half   g_wt16[3][512 * 256];      // transposed weights [256 n][512 k]
__device__ int      g_cnt[CSRTOT];
__device__ int      g_off[CSRTOT];
__device__ int      g_cur[CSRTOT];
__device__ int      g_col[MAXPAIR];
__device__ int      g_bsum[192];

// ---------- helpers ----------
__device__ __forceinline__ float leaky(float a) { return a >= 0.f ? a : 0.01f * a; }

__device__ __forceinline__ void mma_fp16(float c[4], const unsigned a[4], const unsigned b[2]) {
    asm volatile(
        "mma.sync.aligned.m16n8k16.row.col.f32.f16.f16.f32 "
        "{%0,%1,%2,%3},{%4,%5,%6,%7},{%8,%9},{%0,%1,%2,%3};"
        : "+f"(c[0]), "+f"(c[1]), "+f"(c[2]), "+f"(c[3])
        : "r"(a[0]), "r"(a[1]), "r"(a[2]), "r"(a[3]), "r"(b[0]), "r"(b[1]));
}

__device__ __forceinline__ void cp16(void* s, const void* g, bool valid) {
    unsigned saddr = (unsigned)__cvta_generic_to_shared(s);
    int sz = valid ? 16 : 0;
    asm volatile("cp.async.cg.shared.global [%0], [%1], 16, %2;" :: "r"(saddr), "l"(g), "r"(sz));
}
__device__ __forceinline__ void cp_commit() { asm volatile("cp.async.commit_group;"); }
template<int N> __device__ __forceinline__ void cp_wait() { asm volatile("cp.async.wait_group %0;" :: "n"(N)); }

// ---------- embedding body: fp16 output only ----------
template<int W0, int W1, int W2>
__device__ __forceinline__ void embed_body(int blk,
                                           const float* __restrict__ s0,
                                           const float* __restrict__ s1,
                                           const float* __restrict__ s2,
                                           const float* __restrict__ W,
                                           const float* __restrict__ bias,
                                           __half* __restrict__ out16, int n) {
    const int RB = 32;
    const int IN = W0 + W1 + W2;
    __shared__ float xs[RB][IN + 1];
    int row0 = blk * RB;
    int tid = threadIdx.x;
    int cg = tid & 63, rg = tid >> 6;

    for (int i = tid; i < RB * IN; i += 256) {
        int r = i / IN, k = i % IN;
        int row = row0 + r;
        float v = 0.f;
        if (row < n) {
            if (k < W0)            v = s0[(size_t)row * W0 + k];
            else if (k < W0 + W1)  v = s1[(size_t)row * W1 + (k - W0)];
            else                   v = s2[row];
        }
        xs[r][k] = v;
    }
    __syncthreads();

    float4 b = reinterpret_cast<const float4*>(bias)[cg];
    float4 acc[8];
#pragma unroll
    for (int q = 0; q < 8; q++) acc[q] = b;
#pragma unroll
    for (int k = 0; k < IN; k++) {
        float4 w = reinterpret_cast<const float4*>(W + (size_t)k * H)[cg];
#pragma unroll
        for (int q = 0; q < 8; q++) {
            float xv = xs[rg * 8 + q][k];
            acc[q].x += xv * w.x; acc[q].y += xv * w.y;
            acc[q].z += xv * w.z; acc[q].w += xv * w.w;
        }
    }
#pragma unroll
    for (int q = 0; q < 8; q++) {
        int row = row0 + rg * 8 + q;
        if (row < n) {
            uint2 o;
            __half2* oh = reinterpret_cast<__half2*>(&o);
            oh[0] = __floats2half2_rn(leaky(acc[q].x), leaky(acc[q].y));
            oh[1] = __floats2half2_rn(leaky(acc[q].z), leaky(acc[q].w));
            reinterpret_cast<uint2*>(out16 + (size_t)row * H)[cg] = o;
        }
    }
}

// all 4 embeddings in one launch, dispatched by block range
__global__ void embed_all(const float* __restrict__ vp,
                          const float* __restrict__ ec, const float* __restrict__ ecp,
                          const float* __restrict__ ecf,
                          const float* __restrict__ lt,
                          const float* __restrict__ fs, const float* __restrict__ fsp,
                          const float* __restrict__ fsf,
                          const float* __restrict__ Wv, const float* __restrict__ bv,
                          const float* __restrict__ We, const float* __restrict__ be,
                          const float* __restrict__ Wl, const float* __restrict__ bl,
                          const float* __restrict__ Wf, const float* __restrict__ bf,
                          __half* __restrict__ pv16, __half* __restrict__ pe16,
                          __half* __restrict__ pl16, __half* __restrict__ pf16,
                          int NVn, int NEn, int NLn, int NFn,
                          int nbv, int nbe, int nbl) {
    int b = blockIdx.x;
    if (b < nbv)                 embed_body<3, 0, 0>(b, vp, nullptr, nullptr, Wv, bv, pv16, NVn);
    else if (b < nbv + nbe)      embed_body<8, 6, 1>(b - nbv, ec, ecp, ecf, We, be, pe16, NEn);
    else if (b < nbv + nbe + nbl)embed_body<10, 0, 0>(b - nbv - nbe, lt, nullptr, nullptr, Wl, bl, pl16, NLn);
    else                         embed_body<12, 4, 1>(b - nbv - nbe - nbl, fs, fsp, fsf, Wf, bf, pf16, NFn);
}

// ---------- weight transpose: W[512,256] f32 -> Wt16[256,512] f16, z = which W ----------
__global__ void transpose_w3(const float* __restrict__ W0, const float* __restrict__ W1,
                             const float* __restrict__ W2, __half* __restrict__ Wt) {
    __shared__ float t[32][33];
    const float* W = (blockIdx.z == 0) ? W0 : (blockIdx.z == 1) ? W1 : W2;
    __half* O = Wt + (size_t)blockIdx.z * 512 * 256;
    int bx = blockIdx.x * 32;  // k
    int by = blockIdx.y * 32;  // n
    int tx = threadIdx.x, ty = threadIdx.y;  // 32 x 8
#pragma unroll
    for (int i = 0; i < 4; i++)
        t[ty + i * 8][tx] = W[(size_t)(bx + ty + i * 8) * 256 + by + tx];
    __syncthreads();
#pragma unroll
    for (int i = 0; i < 4; i++)
        O[(size_t)(by + ty + i * 8) * 512 + bx + tx] = __float2half_rn(t[tx][ty + i * 8]);
}

// ---------- batched CSR build ----------
__global__ void count_all_kernel(const int* __restrict__ d0, int n0,
                                 const int* __restrict__ d1, int n1,
                                 const int* __restrict__ d2, int n2,
                                 int* __restrict__ cnt) {
    int i = blockIdx.x * blockDim.x + threadIdx.x;
    if (i < n0)                atomicAdd(&cnt[OFF0 + d0[i]], 1);
    else if (i < n0 + n1)      atomicAdd(&cnt[OFF1 + d1[i - n0]], 1);
    else if (i < n0 + n1 + n2) atomicAdd(&cnt[OFF2 + d2[i - n0 - n1]], 1);
}

__global__ void scan_phase1(const int* __restrict__ cnt, int na, int nb_, int nc,
                            int* __restrict__ off, int* __restrict__ bsum) {
    __shared__ int wsum[32];
    int conv = blockIdx.y;
    int n = (conv == 0) ? na : (conv == 1) ? nb_ : nc;
    if (blockIdx.x * 4096 >= n) return;
    int base0 = (conv == 0) ? OFF0 : (conv == 1) ? OFF1 : OFF2;
    const int* c = cnt + base0;
    int* o = off + base0;
    int tid = threadIdx.x, lane = tid & 31, wid = tid >> 5;
    int base = blockIdx.x * 4096 + tid * 4;
    int v0 = (base     < n) ? c[base]     : 0;
    int v1 = (base + 1 < n) ? c[base + 1] : 0;
    int v2 = (base + 2 < n) ? c[base + 2] : 0;
    int v3 = (base + 3 < n) ? c[base + 3] : 0;
    int s = v0 + v1 + v2 + v3;
    int x = s;
#pragma unroll
    for (int d = 1; d < 32; d <<= 1) {
        int y = __shfl_up_sync(~0u, x, d);
        if (lane >= d) x += y;
    }
    if (lane == 31) wsum[wid] = x;
    __syncthreads();
    if (wid == 0) {
        int w = wsum[lane];
#pragma unroll
        for (int d = 1; d < 32; d <<= 1) {
            int y = __shfl_up_sync(~0u, w, d);
            if (lane >= d) w += y;
        }
        wsum[lane] = w;
    }
    __syncthreads();
    int run = x - s + (wid ? wsum[wid - 1] : 0);
    if (base     < n) o[base]     = run; run += v0;
    if (base + 1 < n) o[base + 1] = run; run += v1;
    if (base + 2 < n) o[base + 2] = run; run += v2;
    if (base + 3 < n) o[base + 3] = run;
    if (tid == 0) bsum[conv * 64 + blockIdx.x] = wsum[31];
}

__global__ void scan_phase2(int* __restrict__ bsum, int na, int nb_, int nc,
                            int* __restrict__ off) {
    __shared__ int tmp[64];
    int conv = blockIdx.x;
    int n = (conv == 0) ? na : (conv == 1) ? nb_ : nc;
    int base0 = (conv == 0) ? OFF0 : (conv == 1) ? OFF1 : OFF2;
    int* bs = bsum + conv * 64;
    int nb = (n + 4095) / 4096;
    int tid = threadIdx.x;
    int v = (tid < nb) ? bs[tid] : 0;
    tmp[tid] = v;
    __syncthreads();
    int x = v;
    for (int d = 1; d < 64; d <<= 1) {
        int y = (tid >= d) ? tmp[tid - d] : 0;
        __syncthreads();
        x += y;
        tmp[tid] = x;
        __syncthreads();
    }
    if (tid < nb) bs[tid] = x - v;
    if (tid == 63) off[base0 + n] = x;
}

__global__ void scan_phase3(int* __restrict__ off, const int* __restrict__ bsum,
                            int na, int nb_, int nc, int* __restrict__ cur) {
    int conv = blockIdx.y;
    int n = (conv == 0) ? na : (conv == 1) ? nb_ : nc;
    int i = blockIdx.x * blockDim.x + threadIdx.x;
    if (i >= n) return;
    int base0 = (conv == 0) ? OFF0 : (conv == 1) ? OFF1 : OFF2;
    int o = off[base0 + i] + bsum[conv * 64 + (i >> 12)];
    off[base0 + i] = o;
    cur[base0 + i] = o;
}

__global__ void fill_all_kernel(const int* __restrict__ e0, int n0,
                                const int* __restrict__ e1, int n1,
                                const int* __restrict__ e2, int n2,
                                int* __restrict__ cur, int* __restrict__ col) {
    int i = blockIdx.x * blockDim.x + threadIdx.x;
    const int* idx; int j, np, base0, cbase;
    if (i < n0)                { idx = e0; j = i;           np = n0; base0 = OFF0; cbase = 0; }
    else if (i < n0 + n1)      { idx = e1; j = i - n0;      np = n1; base0 = OFF1; cbase = n0; }
    else if (i < n0 + n1 + n2) { idx = e2; j = i - n0 - n1; np = n2; base0 = OFF2; cbase = n0 + n1; }
    else return;
    int d = idx[j];
    int s = idx[j + np];
    int pos = atomicAdd(&cur[base0 + d], 1);
    col[cbase + pos] = s;
}

// ---------- fused segment-min (fp16, MLP=4) + (x_dst - min) -> fp16 ----------
__global__ void segmin_csr_kernel(const int* __restrict__ off, const int* __restrict__ col,
                                  int n_dst,
                                  const __half* __restrict__ xsrc16,
                                  const __half* __restrict__ xdst16,
                                  __half* __restrict__ mh16) {
    int w = (blockIdx.x * blockDim.x + threadIdx.x) >> 5;
    int lane = threadIdx.x & 31;
    if (w >= n_dst) return;
    int beg = off[w], end = off[w + 1];
    __half2 m[4];
    const __half2 inf2 = __halves2half2(__ushort_as_half(0x7C00), __ushort_as_half(0x7C00));
#pragma unroll
    for (int q = 0; q < 4; q++) m[q] = inf2;

    for (int j = beg; j < end; j += 4) {
        int c0 = col[j];
        int c1 = (j + 1 < end) ? col[j + 1] : c0;
        int c2 = (j + 2 < end) ? col[j + 2] : c0;
        int c3 = (j + 3 < end) ? col[j + 3] : c0;
        uint4 v0 = reinterpret_cast<const uint4*>(xsrc16 + (size_t)c0 * H)[lane];
        uint4 v1 = reinterpret_cast<const uint4*>(xsrc16 + (size_t)c1 * H)[lane];
        uint4 v2 = reinterpret_cast<const uint4*>(xsrc16 + (size_t)c2 * H)[lane];
        uint4 v3 = reinterpret_cast<const uint4*>(xsrc16 + (size_t)c3 * H)[lane];
        const __half2* h0 = reinterpret_cast<const __half2*>(&v0);
        const __half2* h1 = reinterpret_cast<const __half2*>(&v1);
        const __half2* h2 = reinterpret_cast<const __half2*>(&v2);
        const __half2* h3 = reinterpret_cast<const __half2*>(&v3);
#pragma unroll
        for (int q = 0; q < 4; q++) {
            __half2 a = __hmin2(h0[q], h1[q]);
            __half2 b = __hmin2(h2[q], h3[q]);
            m[q] = __hmin2(m[q], __hmin2(a, b));
        }
    }

    uint4 xd = reinterpret_cast<const uint4*>(xdst16 + (size_t)w * H)[lane];
    const __half2* hx = reinterpret_cast<const __half2*>(&xd);
    uint4 outv;
    __half2* oh = reinterpret_cast<__half2*>(&outv);
    if (beg < end) {
#pragma unroll
        for (int q = 0; q < 4; q++) oh[q] = __hsub2(hx[q], m[q]);
    } else {
        outv = make_uint4(0, 0, 0, 0);
    }
    reinterpret_cast<uint4*>(mh16 + (size_t)w * H)[lane] = outv;
}

// ---------- fp16 tensor-core conv GEMM: 128x256 block tile ----------
// 8 warps (2x4), warp tile 64x64, m16n8k16, double-buffered cp.async
#define BM 128
#define BK 32
#define RSTR 20                  // row stride in 32-bit words (16 used + 4 pad)
#define A_WORDS (128 * RSTR)
#define B_WORDS (256 * RSTR)
#define GEMM_SMEM ((2 * A_WORDS + 2 * B_WORDS) * 4)   // 61440 B

__global__ __launch_bounds__(256, 1) void conv_gemm_fp16(const __half* __restrict__ x16,
                                                         const __half* __restrict__ mh16,
                                                         const __half* __restrict__ Wt16,
                                                         const float* __restrict__ bias,
                                                         float* __restrict__ out32,
                                                         __half* __restrict__ out16, int M) {
    extern __shared__ unsigned sm[];
    unsigned* As = sm;
    unsigned* Bs = sm + 2 * A_WORDS;
    int tid = threadIdx.x;
    int warp = tid >> 5, lane = tid & 31;
    int g = lane >> 2, t = lane & 3;
    int wr = warp >> 2, wc = warp & 3;
    int m_w = wr * 64, n_w = wc * 64;
    int bm = blockIdx.x * BM;

    int prow = tid >> 2;
    int pc = tid & 3;

    float c[4][8][4];
#pragma unroll
    for (int i = 0; i < 4; i++)
#pragma unroll
        for (int j = 0; j < 8; j++)
#pragma unroll
            for (int q = 0; q < 4; q++) c[i][j][q] = 0.f;

    auto prefetch = [&](int k0, int buf) {
        const __half* Ab = (k0 < 256) ? x16 : mh16;
        int kk = k0 & 255;
        unsigned* Ad = As + buf * A_WORDS;
        unsigned* Bd = Bs + buf * B_WORDS;
#pragma unroll
        for (int r = 0; r < 2; r++) {
            int row = prow + r * 64;
            bool v = (bm + row) < M;
            const __half* gp = Ab + (size_t)(v ? bm + row : 0) * H + kk + pc * 8;
            cp16(Ad + row * RSTR + pc * 4, gp, v);
        }
#pragma unroll
        for (int r = 0; r < 4; r++) {
            int row = prow + r * 64;
            cp16(Bd + row * RSTR + pc * 4,
                 Wt16 + (size_t)row * 512 + k0 + pc * 8, true);
        }
        cp_commit();
    };

    prefetch(0, 0);

    for (int it = 0; it < 16; it++) {
        int buf = it & 1;
        if (it < 15) {
            prefetch((it + 1) * BK, buf ^ 1);
            cp_wait<1>();
        } else {
            cp_wait<0>();
        }
        __syncthreads();

        const unsigned* Asb = As + buf * A_WORDS;
        const unsigned* Bsb = Bs + buf * B_WORDS;
#pragma unroll
        for (int ks = 0; ks < 2; ks++) {
            int kb2 = ks * 8;
            unsigned a[4][4], b[8][2];
#pragma unroll
            for (int i = 0; i < 4; i++) {
                int mb = m_w + i * 16;
                a[i][0] = Asb[(mb + g) * RSTR + kb2 + t];
                a[i][1] = Asb[(mb + g + 8) * RSTR + kb2 + t];
                a[i][2] = Asb[(mb + g) * RSTR + kb2 + 4 + t];
                a[i][3] = Asb[(mb + g + 8) * RSTR + kb2 + 4 + t];
            }
#pragma unroll
            for (int j = 0; j < 8; j++) {
                int nb = n_w + j * 8;
                b[j][0] = Bsb[(nb + g) * RSTR + kb2 + t];
                b[j][1] = Bsb[(nb + g) * RSTR + kb2 + 4 + t];
            }
#pragma unroll
            for (int i = 0; i < 4; i++)
#pragma unroll
                for (int j = 0; j < 8; j++) mma_fp16(c[i][j], a[i], b[j]);
        }
        __syncthreads();
    }

    // epilogue: out = x16 + leaky(c + bias)
#pragma unroll
    for (int i = 0; i < 4; i++) {
        int r0 = bm + m_w + i * 16 + g;
        int r1 = r0 + 8;
#pragma unroll
        for (int j = 0; j < 8; j++) {
            int col = n_w + j * 8 + t * 2;
            float b0 = bias[col], b1 = bias[col + 1];
            if (r0 < M) {
                size_t o = (size_t)r0 * H + col;
                float2 xf = __half22float2(*reinterpret_cast<const __half2*>(x16 + o));
                float v0 = xf.x + leaky(c[i][j][0] + b0);
                float v1 = xf.y + leaky(c[i][j][1] + b1);
                if (out32) { out32[o] = v0; out32[o + 1] = v1; }
                if (out16) *reinterpret_cast<__half2*>(out16 + o) = __floats2half2_rn(v0, v1);
            }
            if (r1 < M) {
                size_t o = (size_t)r1 * H + col;
                float2 xf = __half22float2(*reinterpret_cast<const __half2*>(x16 + o));
                float v0 = xf.x + leaky(c[i][j][2] + b0);
                float v1 = xf.y + leaky(c[i][j][3] + b1);
                if (out32) { out32[o] = v0; out32[o + 1] = v1; }
                if (out16) *reinterpret_cast<__half2*>(out16 + o) = __floats2half2_rn(v0, v1);
            }
        }
    }
}

// ---------- launch ----------
static inline int cdiv(int a, int b) { return (a + b - 1) / b; }

extern "C" void kernel_launch(void* const* d_in, const int* in_sizes, int n_in,
                              void* d_out, int out_size) {
    const float* vp  = (const float*)d_in[0];
    const float* ec  = (const float*)d_in[1];
    const float* ecp = (const float*)d_in[2];
    const float* ecf = (const float*)d_in[3];
    const float* lt  = (const float*)d_in[4];
    const float* fs  = (const float*)d_in[5];
    const float* fsp = (const float*)d_in[6];
    const float* fsf = (const float*)d_in[7];
    const int* ev = (const int*)d_in[8];
    const int* le = (const int*)d_in[9];
    const int* fl = (const int*)d_in[10];
    const float* Wv = (const float*)d_in[11]; const float* bv = (const float*)d_in[12];
    const float* We = (const float*)d_in[13]; const float* be = (const float*)d_in[14];
    const float* Wl = (const float*)d_in[15]; const float* bl = (const float*)d_in[16];
    const float* Wf = (const float*)d_in[17]; const float* bf = (const float*)d_in[18];
    const float* Wve = (const float*)d_in[19]; const float* bve = (const float*)d_in[20];
    const float* Wel = (const float*)d_in[21]; const float* bel = (const float*)d_in[22];
    const float* Wlf = (const float*)d_in[23]; const float* blf = (const float*)d_in[24];

    int NVn = in_sizes[0] / 3;
    int NEn = in_sizes[1] / 8;
    int NLn = in_sizes[4] / 10;
    int NFn = in_sizes[5] / 12;
    int nEV = in_sizes[8] / 2;
    int nLE = in_sizes[9] / 2;
    int nFL = in_sizes[10] / 2;

    __half *pv16, *pe16, *peo16, *pl16, *pf16, *pmh16, *pwt16;
    int *pcnt, *poff, *pcur, *pcol, *pbsum;
    cudaGetSymbolAddress((void**)&pv16,  g_v16);
    cudaGetSymbolAddress((void**)&pe16,  g_e16);
    cudaGetSymbolAddress((void**)&peo16, g_eo16);
    cudaGetSymbolAddress((void**)&pl16,  g_l16);
    cudaGetSymbolAddress((void**)&pf16,  g_f16);
    cudaGetSymbolAddress((void**)&pmh16, g_mh16);
    cudaGetSymbolAddress((void**)&pwt16, g_wt16);
    cudaGetSymbolAddress((void**)&pcnt,  g_cnt);
    cudaGetSymbolAddress((void**)&poff,  g_off);
    cudaGetSymbolAddress((void**)&pcur,  g_cur);
    cudaGetSymbolAddress((void**)&pcol,  g_col);
    cudaGetSymbolAddress((void**)&pbsum, g_bsum);

    cudaFuncSetAttribute(conv_gemm_fp16, cudaFuncAttributeMaxDynamicSharedMemorySize, GEMM_SMEM);

    int nPairTot = nEV + nLE + nFL;
    int nmax = NEn;

    // weight transposes (one launch)
    {
        dim3 g(16, 8, 3), b(32, 8);
        transpose_w3<<<g, b>>>(Wve, Wel, Wlf, pwt16);
    }

    // batched CSR build
    cudaMemsetAsync(pcnt, 0, (size_t)CSRTOT * sizeof(int));
    count_all_kernel<<<cdiv(nPairTot, 256), 256>>>(ev, nEV, le, nLE, fl, nFL, pcnt);
    {
        dim3 g1(cdiv(nmax, 4096), 3);
        scan_phase1<<<g1, 1024>>>(pcnt, NEn, NLn, NFn, poff, pbsum);
        scan_phase2<<<3, 64>>>(pbsum, NEn, NLn, NFn, poff);
        dim3 g3(cdiv(nmax, 256), 3);
        scan_phase3<<<g3, 256>>>(poff, pbsum, NEn, NLn, NFn, pcur);
    }
    fill_all_kernel<<<cdiv(nPairTot, 256), 256>>>(ev, nEV, le, nLE, fl, nFL, pcur, pcol);

    // embeddings: all four in one launch, fp16 outputs only
    {
        int nbv = cdiv(NVn, 32), nbe = cdiv(NEn, 32), nbl = cdiv(NLn, 32), nbf = cdiv(NFn, 32);
        embed_all<<<nbv + nbe + nbl + nbf, 256>>>(vp, ec, ecp, ecf, lt, fs, fsp, fsf,
                                                  Wv, bv, We, be, Wl, bl, Wf, bf,
                                                  pv16, pe16, pl16, pf16,
                                                  NVn, NEn, NLn, NFn, nbv, nbe, nbl);
    }

    // conv 1: vertices -> edges
    segmin_csr_kernel<<<cdiv(NEn * 32, 256), 256>>>(poff + OFF0, pcol, NEn, pv16, pe16, pmh16);
    conv_gemm_fp16<<<cdiv(NEn, BM), 256, GEMM_SMEM>>>(pe16, pmh16, pwt16, bve, nullptr, peo16, NEn);

    // conv 2: edges -> loops (fp16 out reuses g_v16)
    segmin_csr_kernel<<<cdiv(NLn * 32, 256), 256>>>(poff + OFF1, pcol + nEV, NLn, peo16, pl16, pmh16);
    conv_gemm_fp16<<<cdiv(NLn, BM), 256, GEMM_SMEM>>>(pl16, pmh16, pwt16 + 512 * 256, bel, nullptr, pv16, NLn);

    // conv 3: loops -> faces (fp32 output = d_out)
    segmin_csr_kernel<<<cdiv(NFn * 32, 256), 256>>>(poff + OFF2, pcol + nEV + nLE, NFn, pv16, pf16, pmh16);
    conv_gemm_fp16<<<cdiv(NFn, BM), 256, GEMM_SMEM>>>(pf16, pmh16, pwt16 + 2 * 512 * 256, blf, (float*)d_out, nullptr, NFn);
}

// round 10
// speedup vs baseline: 1.5117x; 1.0788x over previous
#include <cuda_runtime.h>
#include <cuda_fp16.h>
#include <cstdint>

#define H 256

#define MAXV 100000
#define MAXE 150000
#define MAXL 80000
#define MAXF 60000
#define MAXPAIR 800000

#define OFF0 0
#define OFF1 (MAXE + 1)
#define OFF2 (MAXE + 1 + MAXL + 1)
#define CSRTOT (MAXE + MAXL + MAXF + 3)

// scratch (fp16 activations only)
__device__ __half   g_v16[(size_t)MAXV * H];   // vertex embed; reused as conv2-output
__device__ __half   g_e16[(size_t)MAXE * H];
__device__ __half   g_eo16[(size_t)MAXE * H];  // conv1 output
__device__ __half   g_l16[(size_t)MAXL * H];
__device__ __half   g_f16[(size_t)MAXF * H];
__device__ __half   g_mh16[(size_t)MAXE * H];
__device__ __half   g_wt16[3][512 * 256];      // transposed weights [256 n][512 k]
__device__ int      g_cnt[CSRTOT];
__device__ int      g_off[CSRTOT];
__device__ int      g_cur[CSRTOT];
__device__ int      g_col[MAXPAIR];
__device__ int      g_bsum[192];

// ---------- helpers ----------
__device__ __forceinline__ float leaky(float a) { return a >= 0.f ? a : 0.01f * a; }

__device__ __forceinline__ void mma_fp16(float c[4], const unsigned a[4], const unsigned b[2]) {
    asm volatile(
        "mma.sync.aligned.m16n8k16.row.col.f32.f16.f16.f32 "
        "{%0,%1,%2,%3},{%4,%5,%6,%7},{%8,%9},{%0,%1,%2,%3};"
        : "+f"(c[0]), "+f"(c[1]), "+f"(c[2]), "+f"(c[3])
        : "r"(a[0]), "r"(a[1]), "r"(a[2]), "r"(a[3]), "r"(b[0]), "r"(b[1]));
}

__device__ __forceinline__ void ldsm_x4(unsigned& r0, unsigned& r1, unsigned& r2, unsigned& r3,
                                        unsigned addr) {
    asm volatile("ldmatrix.sync.aligned.m8n8.x4.shared.b16 {%0,%1,%2,%3}, [%4];"
                 : "=r"(r0), "=r"(r1), "=r"(r2), "=r"(r3) : "r"(addr));
}

__device__ __forceinline__ void cp16(void* s, const void* g, bool valid) {
    unsigned saddr = (unsigned)__cvta_generic_to_shared(s);
    int sz = valid ? 16 : 0;
    asm volatile("cp.async.cg.shared.global [%0], [%1], 16, %2;" :: "r"(saddr), "l"(g), "r"(sz));
}
__device__ __forceinline__ void cp_commit() { asm volatile("cp.async.commit_group;"); }
template<int N> __device__ __forceinline__ void cp_wait() { asm volatile("cp.async.wait_group %0;" :: "n"(N)); }

// ---------- embedding body: fp16 output only ----------
template<int W0, int W1, int W2>
__device__ __forceinline__ void embed_body(int blk,
                                           const float* __restrict__ s0,
                                           const float* __restrict__ s1,
                                           const float* __restrict__ s2,
                                           const float* __restrict__ W,
                                           const float* __restrict__ bias,
                                           __half* __restrict__ out16, int n) {
    const int RB = 32;
    const int IN = W0 + W1 + W2;
    __shared__ float xs[RB][IN + 1];
    int row0 = blk * RB;
    int tid = threadIdx.x;
    int cg = tid & 63, rg = tid >> 6;

    for (int i = tid; i < RB * IN; i += 256) {
        int r = i / IN, k = i % IN;
        int row = row0 + r;
        float v = 0.f;
        if (row < n) {
            if (k < W0)            v = s0[(size_t)row * W0 + k];
            else if (k < W0 + W1)  v = s1[(size_t)row * W1 + (k - W0)];
            else                   v = s2[row];
        }
        xs[r][k] = v;
    }
    __syncthreads();

    float4 b = reinterpret_cast<const float4*>(bias)[cg];
    float4 acc[8];
#pragma unroll
    for (int q = 0; q < 8; q++) acc[q] = b;
#pragma unroll
    for (int k = 0; k < IN; k++) {
        float4 w = reinterpret_cast<const float4*>(W + (size_t)k * H)[cg];
#pragma unroll
        for (int q = 0; q < 8; q++) {
            float xv = xs[rg * 8 + q][k];
            acc[q].x += xv * w.x; acc[q].y += xv * w.y;
            acc[q].z += xv * w.z; acc[q].w += xv * w.w;
        }
    }
#pragma unroll
    for (int q = 0; q < 8; q++) {
        int row = row0 + rg * 8 + q;
        if (row < n) {
            uint2 o;
            __half2* oh = reinterpret_cast<__half2*>(&o);
            oh[0] = __floats2half2_rn(leaky(acc[q].x), leaky(acc[q].y));
            oh[1] = __floats2half2_rn(leaky(acc[q].z), leaky(acc[q].w));
            reinterpret_cast<uint2*>(out16 + (size_t)row * H)[cg] = o;
        }
    }
}

// all 4 embeddings in one launch
__global__ void embed_all(const float* __restrict__ vp,
                          const float* __restrict__ ec, const float* __restrict__ ecp,
                          const float* __restrict__ ecf,
                          const float* __restrict__ lt,
                          const float* __restrict__ fs, const float* __restrict__ fsp,
                          const float* __restrict__ fsf,
                          const float* __restrict__ Wv, const float* __restrict__ bv,
                          const float* __restrict__ We, const float* __restrict__ be,
                          const float* __restrict__ Wl, const float* __restrict__ bl,
                          const float* __restrict__ Wf, const float* __restrict__ bf,
                          __half* __restrict__ pv16, __half* __restrict__ pe16,
                          __half* __restrict__ pl16, __half* __restrict__ pf16,
                          int NVn, int NEn, int NLn, int NFn,
                          int nbv, int nbe, int nbl) {
    int b = blockIdx.x;
    if (b < nbv)                 embed_body<3, 0, 0>(b, vp, nullptr, nullptr, Wv, bv, pv16, NVn);
    else if (b < nbv + nbe)      embed_body<8, 6, 1>(b - nbv, ec, ecp, ecf, We, be, pe16, NEn);
    else if (b < nbv + nbe + nbl)embed_body<10, 0, 0>(b - nbv - nbe, lt, nullptr, nullptr, Wl, bl, pl16, NLn);
    else                         embed_body<12, 4, 1>(b - nbv - nbe - nbl, fs, fsp, fsf, Wf, bf, pf16, NFn);
}

// ---------- weight transpose ----------
__global__ void transpose_w3(const float* __restrict__ W0, const float* __restrict__ W1,
                             const float* __restrict__ W2, __half* __restrict__ Wt) {
    __shared__ float t[32][33];
    const float* W = (blockIdx.z == 0) ? W0 : (blockIdx.z == 1) ? W1 : W2;
    __half* O = Wt + (size_t)blockIdx.z * 512 * 256;
    int bx = blockIdx.x * 32;
    int by = blockIdx.y * 32;
    int tx = threadIdx.x, ty = threadIdx.y;
#pragma unroll
    for (int i = 0; i < 4; i++)
        t[ty + i * 8][tx] = W[(size_t)(bx + ty + i * 8) * 256 + by + tx];
    __syncthreads();
#pragma unroll
    for (int i = 0; i < 4; i++)
        O[(size_t)(by + ty + i * 8) * 512 + bx + tx] = __float2half_rn(t[tx][ty + i * 8]);
}

// ---------- batched CSR build ----------
__global__ void count_all_kernel(const int* __restrict__ d0, int n0,
                                 const int* __restrict__ d1, int n1,
                                 const int* __restrict__ d2, int n2,
                                 int* __restrict__ cnt) {
    int i = blockIdx.x * blockDim.x + threadIdx.x;
    if (i < n0)                atomicAdd(&cnt[OFF0 + d0[i]], 1);
    else if (i < n0 + n1)      atomicAdd(&cnt[OFF1 + d1[i - n0]], 1);
    else if (i < n0 + n1 + n2) atomicAdd(&cnt[OFF2 + d2[i - n0 - n1]], 1);
}

__global__ void scan_phase1(const int* __restrict__ cnt, int na, int nb_, int nc,
                            int* __restrict__ off, int* __restrict__ bsum) {
    __shared__ int wsum[32];
    int conv = blockIdx.y;
    int n = (conv == 0) ? na : (conv == 1) ? nb_ : nc;
    if (blockIdx.x * 4096 >= n) return;
    int base0 = (conv == 0) ? OFF0 : (conv == 1) ? OFF1 : OFF2;
    const int* c = cnt + base0;
    int* o = off + base0;
    int tid = threadIdx.x, lane = tid & 31, wid = tid >> 5;
    int base = blockIdx.x * 4096 + tid * 4;
    int v0 = (base     < n) ? c[base]     : 0;
    int v1 = (base + 1 < n) ? c[base + 1] : 0;
    int v2 = (base + 2 < n) ? c[base + 2] : 0;
    int v3 = (base + 3 < n) ? c[base + 3] : 0;
    int s = v0 + v1 + v2 + v3;
    int x = s;
#pragma unroll
    for (int d = 1; d < 32; d <<= 1) {
        int y = __shfl_up_sync(~0u, x, d);
        if (lane >= d) x += y;
    }
    if (lane == 31) wsum[wid] = x;
    __syncthreads();
    if (wid == 0) {
        int w = wsum[lane];
#pragma unroll
        for (int d = 1; d < 32; d <<= 1) {
            int y = __shfl_up_sync(~0u, w, d);
            if (lane >= d) w += y;
        }
        wsum[lane] = w;
    }
    __syncthreads();
    int run = x - s + (wid ? wsum[wid - 1] : 0);
    if (base     < n) o[base]     = run; run += v0;
    if (base + 1 < n) o[base + 1] = run; run += v1;
    if (base + 2 < n) o[base + 2] = run; run += v2;
    if (base + 3 < n) o[base + 3] = run;
    if (tid == 0) bsum[conv * 64 + blockIdx.x] = wsum[31];
}

__global__ void scan_phase2(int* __restrict__ bsum, int na, int nb_, int nc,
                            int* __restrict__ off) {
    __shared__ int tmp[64];
    int conv = blockIdx.x;
    int n = (conv == 0) ? na : (conv == 1) ? nb_ : nc;
    int base0 = (conv == 0) ? OFF0 : (conv == 1) ? OFF1 : OFF2;
    int* bs = bsum + conv * 64;
    int nb = (n + 4095) / 4096;
    int tid = threadIdx.x;
    int v = (tid < nb) ? bs[tid] : 0;
    tmp[tid] = v;
    __syncthreads();
    int x = v;
    for (int d = 1; d < 64; d <<= 1) {
        int y = (tid >= d) ? tmp[tid - d] : 0;
        __syncthreads();
        x += y;
        tmp[tid] = x;
        __syncthreads();
    }
    if (tid < nb) bs[tid] = x - v;
    if (tid == 63) off[base0 + n] = x;
}

__global__ void scan_phase3(int* __restrict__ off, const int* __restrict__ bsum,
                            int na, int nb_, int nc, int* __restrict__ cur) {
    int conv = blockIdx.y;
    int n = (conv == 0) ? na : (conv == 1) ? nb_ : nc;
    int i = blockIdx.x * blockDim.x + threadIdx.x;
    if (i >= n) return;
    int base0 = (conv == 0) ? OFF0 : (conv == 1) ? OFF1 : OFF2;
    int o = off[base0 + i] + bsum[conv * 64 + (i >> 12)];
    off[base0 + i] = o;
    cur[base0 + i] = o;
}

__global__ void fill_all_kernel(const int* __restrict__ e0, int n0,
                                const int* __restrict__ e1, int n1,
                                const int* __restrict__ e2, int n2,
                                int* __restrict__ cur, int* __restrict__ col) {
    int i = blockIdx.x * blockDim.x + threadIdx.x;
    const int* idx; int j, np, base0, cbase;
    if (i < n0)                { idx = e0; j = i;           np = n0; base0 = OFF0; cbase = 0; }
    else if (i < n0 + n1)      { idx = e1; j = i - n0;      np = n1; base0 = OFF1; cbase = n0; }
    else if (i < n0 + n1 + n2) { idx = e2; j = i - n0 - n1; np = n2; base0 = OFF2; cbase = n0 + n1; }
    else return;
    int d = idx[j];
    int s = idx[j + np];
    int pos = atomicAdd(&cur[base0 + d], 1);
    col[cbase + pos] = s;
}

// ---------- fused segment-min (fp16, MLP=4) + (x_dst - min) -> fp16 ----------
__global__ void segmin_csr_kernel(const int* __restrict__ off, const int* __restrict__ col,
                                  int n_dst,
                                  const __half* __restrict__ xsrc16,
                                  const __half* __restrict__ xdst16,
                                  __half* __restrict__ mh16) {
    int w = (blockIdx.x * blockDim.x + threadIdx.x) >> 5;
    int lane = threadIdx.x & 31;
    if (w >= n_dst) return;
    int beg = off[w], end = off[w + 1];
    __half2 m[4];
    const __half2 inf2 = __halves2half2(__ushort_as_half(0x7C00), __ushort_as_half(0x7C00));
#pragma unroll
    for (int q = 0; q < 4; q++) m[q] = inf2;

    for (int j = beg; j < end; j += 4) {
        int c0 = col[j];
        int c1 = (j + 1 < end) ? col[j + 1] : c0;
        int c2 = (j + 2 < end) ? col[j + 2] : c0;
        int c3 = (j + 3 < end) ? col[j + 3] : c0;
        uint4 v0 = reinterpret_cast<const uint4*>(xsrc16 + (size_t)c0 * H)[lane];
        uint4 v1 = reinterpret_cast<const uint4*>(xsrc16 + (size_t)c1 * H)[lane];
        uint4 v2 = reinterpret_cast<const uint4*>(xsrc16 + (size_t)c2 * H)[lane];
        uint4 v3 = reinterpret_cast<const uint4*>(xsrc16 + (size_t)c3 * H)[lane];
        const __half2* h0 = reinterpret_cast<const __half2*>(&v0);
        const __half2* h1 = reinterpret_cast<const __half2*>(&v1);
        const __half2* h2 = reinterpret_cast<const __half2*>(&v2);
        const __half2* h3 = reinterpret_cast<const __half2*>(&v3);
#pragma unroll
        for (int q = 0; q < 4; q++) {
            __half2 a = __hmin2(h0[q], h1[q]);
            __half2 b = __hmin2(h2[q], h3[q]);
            m[q] = __hmin2(m[q], __hmin2(a, b));
        }
    }

    uint4 xd = reinterpret_cast<const uint4*>(xdst16 + (size_t)w * H)[lane];
    const __half2* hx = reinterpret_cast<const __half2*>(&xd);
    uint4 outv;
    __half2* oh = reinterpret_cast<__half2*>(&outv);
    if (beg < end) {
#pragma unroll
        for (int q = 0; q < 4; q++) oh[q] = __hsub2(hx[q], m[q]);
    } else {
        outv = make_uint4(0, 0, 0, 0);
    }
    reinterpret_cast<uint4*>(mh16 + (size_t)w * H)[lane] = outv;
}

// ---------- fp16 tensor-core conv GEMM: 128x256 tile, ldmatrix, 4-stage cp.async ----------
#define BM 128
#define BK 32
#define RSTR 20                     // row stride in 32-bit words (16 used + 4 pad)
#define A_WORDS (128 * RSTR)        // 2560
#define B_WORDS (256 * RSTR)        // 5120
#define STG_WORDS (A_WORDS + B_WORDS)
#define STG_BYTES (STG_WORDS * 4)   // 30720
#define GEMM_SMEM (4 * STG_BYTES)   // 122880

__global__ __launch_bounds__(256, 1) void conv_gemm_fp16(const __half* __restrict__ x16,
                                                         const __half* __restrict__ mh16,
                                                         const __half* __restrict__ Wt16,
                                                         const float* __restrict__ bias,
                                                         float* __restrict__ out32,
                                                         __half* __restrict__ out16, int M) {
    extern __shared__ unsigned sm[];
    int tid = threadIdx.x;
    int warp = tid >> 5, lane = tid & 31;
    int g = lane >> 2, t = lane & 3;
    int wr = warp >> 2, wc = warp & 3;
    int m_w = wr * 64, n_w = wc * 64;
    int bm = blockIdx.x * BM;

    int prow = tid >> 2;
    int pc = tid & 3;

    float c[4][8][4];
#pragma unroll
    for (int i = 0; i < 4; i++)
#pragma unroll
        for (int j = 0; j < 8; j++)
#pragma unroll
            for (int q = 0; q < 4; q++) c[i][j][q] = 0.f;

    auto prefetch = [&](int tile, int slot) {
        int k0 = tile * BK;
        const __half* Ab = (k0 < 256) ? x16 : mh16;
        int kk = k0 & 255;
        unsigned* Ad = sm + slot * STG_WORDS;
        unsigned* Bd = Ad + A_WORDS;
#pragma unroll
        for (int r = 0; r < 2; r++) {
            int row = prow + r * 64;
            bool v = (bm + row) < M;
            const __half* gp = Ab + (size_t)(v ? bm + row : 0) * H + kk + pc * 8;
            cp16(Ad + row * RSTR + pc * 4, gp, v);
        }
#pragma unroll
        for (int r = 0; r < 4; r++) {
            int row = prow + r * 64;
            cp16(Bd + row * RSTR + pc * 4,
                 Wt16 + (size_t)row * 512 + k0 + pc * 8, true);
        }
        cp_commit();
    };

    prefetch(0, 0);
    prefetch(1, 1);
    prefetch(2, 2);

    unsigned sb = (unsigned)__cvta_generic_to_shared(sm);
    // per-lane ldmatrix base offsets (within a stage), in bytes
    unsigned aOff = (unsigned)((m_w + (lane & 15)) * RSTR) * 4 + (unsigned)(lane >> 4) * 16;
    unsigned bOff = (unsigned)A_WORDS * 4 +
                    (unsigned)((n_w + (lane & 7) + ((lane >> 4) << 3)) * RSTR) * 4 +
                    (unsigned)((lane >> 3) & 1) * 16;

    for (int it = 0; it < 16; it++) {
        if (it <= 13) cp_wait<2>();
        else if (it == 14) cp_wait<1>();
        else cp_wait<0>();
        __syncthreads();

        int slot = it & 3;
        unsigned aBase = sb + slot * STG_BYTES + aOff;
        unsigned bBase = sb + slot * STG_BYTES + bOff;
#pragma unroll
        for (int ks = 0; ks < 2; ks++) {
            unsigned kB = ks * 32;
            unsigned a[4][4], b[8][2];
#pragma unroll
            for (int i = 0; i < 4; i++)
                ldsm_x4(a[i][0], a[i][1], a[i][2], a[i][3], aBase + i * (16 * RSTR * 4) + kB);
#pragma unroll
            for (int jj = 0; jj < 4; jj++)
                ldsm_x4(b[2 * jj][0], b[2 * jj][1], b[2 * jj + 1][0], b[2 * jj + 1][1],
                        bBase + jj * (16 * RSTR * 4) + kB);
#pragma unroll
            for (int i = 0; i < 4; i++)
#pragma unroll
                for (int j = 0; j < 8; j++) mma_fp16(c[i][j], a[i], b[j]);
        }

        if (it + 3 <= 15) prefetch(it + 3, (it + 3) & 3);
    }

    // epilogue: out = x16 + leaky(c + bias)
#pragma unroll
    for (int i = 0; i < 4; i++) {
        int r0 = bm + m_w + i * 16 + g;
        int r1 = r0 + 8;
#pragma unroll
        for (int j = 0; j < 8; j++) {
            int col = n_w + j * 8 + t * 2;
            float b0 = bias[col], b1 = bias[col + 1];
            if (r0 < M) {
                size_t o = (size_t)r0 * H + col;
                float2 xf = __half22float2(*reinterpret_cast<const __half2*>(x16 + o));
                float v0 = xf.x + leaky(c[i][j][0] + b0);
                float v1 = xf.y + leaky(c[i][j][1] + b1);
                if (out32) { out32[o] = v0; out32[o + 1] = v1; }
                if (out16) *reinterpret_cast<__half2*>(out16 + o) = __floats2half2_rn(v0, v1);
            }
            if (r1 < M) {
                size_t o = (size_t)r1 * H + col;
                float2 xf = __half22float2(*reinterpret_cast<const __half2*>(x16 + o));
                float v0 = xf.x + leaky(c[i][j][2] + b0);
                float v1 = xf.y + leaky(c[i][j][3] + b1);
                if (out32) { out32[o] = v0; out32[o + 1] = v1; }
                if (out16) *reinterpret_cast<__half2*>(out16 + o) = __floats2half2_rn(v0, v1);
            }
        }
    }
}

// ---------- launch ----------
static inline int cdiv(int a, int b) { return (a + b - 1) / b; }

extern "C" void kernel_launch(void* const* d_in, const int* in_sizes, int n_in,
                              void* d_out, int out_size) {
    const float* vp  = (const float*)d_in[0];
    const float* ec  = (const float*)d_in[1];
    const float* ecp = (const float*)d_in[2];
    const float* ecf = (const float*)d_in[3];
    const float* lt  = (const float*)d_in[4];
    const float* fs  = (const float*)d_in[5];
    const float* fsp = (const float*)d_in[6];
    const float* fsf = (const float*)d_in[7];
    const int* ev = (const int*)d_in[8];
    const int* le = (const int*)d_in[9];
    const int* fl = (const int*)d_in[10];
    const float* Wv = (const float*)d_in[11]; const float* bv = (const float*)d_in[12];
    const float* We = (const float*)d_in[13]; const float* be = (const float*)d_in[14];
    const float* Wl = (const float*)d_in[15]; const float* bl = (const float*)d_in[16];
    const float* Wf = (const float*)d_in[17]; const float* bf = (const float*)d_in[18];
    const float* Wve = (const float*)d_in[19]; const float* bve = (const float*)d_in[20];
    const float* Wel = (const float*)d_in[21]; const float* bel = (const float*)d_in[22];
    const float* Wlf = (const float*)d_in[23]; const float* blf = (const float*)d_in[24];

    int NVn = in_sizes[0] / 3;
    int NEn = in_sizes[1] / 8;
    int NLn = in_sizes[4] / 10;
    int NFn = in_sizes[5] / 12;
    int nEV = in_sizes[8] / 2;
    int nLE = in_sizes[9] / 2;
    int nFL = in_sizes[10] / 2;

    __half *pv16, *pe16, *peo16, *pl16, *pf16, *pmh16, *pwt16;
    int *pcnt, *poff, *pcur, *pcol, *pbsum;
    cudaGetSymbolAddress((void**)&pv16,  g_v16);
    cudaGetSymbolAddress((void**)&pe16,  g_e16);
    cudaGetSymbolAddress((void**)&peo16, g_eo16);
    cudaGetSymbolAddress((void**)&pl16,  g_l16);
    cudaGetSymbolAddress((void**)&pf16,  g_f16);
    cudaGetSymbolAddress((void**)&pmh16, g_mh16);
    cudaGetSymbolAddress((void**)&pwt16, g_wt16);
    cudaGetSymbolAddress((void**)&pcnt,  g_cnt);
    cudaGetSymbolAddress((void**)&poff,  g_off);
    cudaGetSymbolAddress((void**)&pcur,  g_cur);
    cudaGetSymbolAddress((void**)&pcol,  g_col);
    cudaGetSymbolAddress((void**)&pbsum, g_bsum);

    cudaFuncSetAttribute(conv_gemm_fp16, cudaFuncAttributeMaxDynamicSharedMemorySize, GEMM_SMEM);

    int nPairTot = nEV + nLE + nFL;
    int nmax = NEn;

    // weight transposes (one launch)
    {
        dim3 g(16, 8, 3), b(32, 8);
        transpose_w3<<<g, b>>>(Wve, Wel, Wlf, pwt16);
    }

    // batched CSR build
    cudaMemsetAsync(pcnt, 0, (size_t)CSRTOT * sizeof(int));
    count_all_kernel<<<cdiv(nPairTot, 256), 256>>>(ev, nEV, le, nLE, fl, nFL, pcnt);
    {
        dim3 g1(cdiv(nmax, 4096), 3);
        scan_phase1<<<g1, 1024>>>(pcnt, NEn, NLn, NFn, poff, pbsum);
        scan_phase2<<<3, 64>>>(pbsum, NEn, NLn, NFn, poff);
        dim3 g3(cdiv(nmax, 256), 3);
        scan_phase3<<<g3, 256>>>(poff, pbsum, NEn, NLn, NFn, pcur);
    }
    fill_all_kernel<<<cdiv(nPairTot, 256), 256>>>(ev, nEV, le, nLE, fl, nFL, pcur, pcol);

    // embeddings: all four in one launch, fp16 outputs only
    {
        int nbv = cdiv(NVn, 32), nbe = cdiv(NEn, 32), nbl = cdiv(NLn, 32), nbf = cdiv(NFn, 32);
        embed_all<<<nbv + nbe + nbl + nbf, 256>>>(vp, ec, ecp, ecf, lt, fs, fsp, fsf,
                                                  Wv, bv, We, be, Wl, bl, Wf, bf,
                                                  pv16, pe16, pl16, pf16,
                                                  NVn, NEn, NLn, NFn, nbv, nbe, nbl);
    }

    // conv 1: vertices -> edges
    segmin_csr_kernel<<<cdiv(NEn * 32, 256), 256>>>(poff + OFF0, pcol, NEn, pv16, pe16, pmh16);
    conv_gemm_fp16<<<cdiv(NEn, BM), 256, GEMM_SMEM>>>(pe16, pmh16, pwt16, bve, nullptr, peo16, NEn);

    // conv 2: edges -> loops (fp16 out reuses g_v16)
    segmin_csr_kernel<<<cdiv(NLn * 32, 256), 256>>>(poff + OFF1, pcol + nEV, NLn, peo16, pl16, pmh16);
    conv_gemm_fp16<<<cdiv(NLn, BM), 256, GEMM_SMEM>>>(pl16, pmh16, pwt16 + 512 * 256, bel, nullptr, pv16, NLn);

    // conv 3: loops -> faces (fp32 output = d_out)
    segmin_csr_kernel<<<cdiv(NFn * 32, 256), 256>>>(poff + OFF2, pcol + nEV + nLE, NFn, pv16, pf16, pmh16);
    conv_gemm_fp16<<<cdiv(NFn, BM), 256, GEMM_SMEM>>>(pf16, pmh16, pwt16 + 2 * 512 * 256, blf, (float*)d_out, nullptr, NFn);
}

// round 11
// speedup vs baseline: 1.5626x; 1.0337x over previous
#include <cuda_runtime.h>
#include <cuda_fp16.h>
#include <cstdint>

#define H 256

#define MAXV 100000
#define MAXE 150000
#define MAXL 80000
#define MAXF 60000
#define MAXPAIR 800000

#define OFF0 0
#define OFF1 (MAXE + 1)
#define OFF2 (MAXE + 1 + MAXL + 1)
#define CSRTOT (MAXE + MAXL + MAXF + 3)

// scratch (fp16 activations only)
__device__ __half   g_v16[(size_t)MAXV * H];   // vertex embed; reused as conv2-output
__device__ __half   g_e16[(size_t)MAXE * H];
__device__ __half   g_eo16[(size_t)MAXE * H];  // conv1 output
__device__ __half   g_l16[(size_t)MAXL * H];
__device__ __half   g_f16[(size_t)MAXF * H];
__device__ __half   g_mh16[(size_t)MAXE * H];
__device__ __half   g_wt16[3][512 * 256];      // transposed weights [256 n][512 k]
__device__ int      g_cnt[CSRTOT];
__device__ int      g_off[CSRTOT];
__device__ int      g_cur[CSRTOT];
__device__ int      g_col[MAXPAIR];
__device__ int      g_bsum[192];

// ---------- helpers ----------
__device__ __forceinline__ float leaky(float a) { return a >= 0.f ? a : 0.01f * a; }

__device__ __forceinline__ void mma_fp16(float c[4], const unsigned a[4], const unsigned b[2]) {
    asm volatile(
        "mma.sync.aligned.m16n8k16.row.col.f32.f16.f16.f32 "
        "{%0,%1,%2,%3},{%4,%5,%6,%7},{%8,%9},{%0,%1,%2,%3};"
        : "+f"(c[0]), "+f"(c[1]), "+f"(c[2]), "+f"(c[3])
        : "r"(a[0]), "r"(a[1]), "r"(a[2]), "r"(a[3]), "r"(b[0]), "r"(b[1]));
}

__device__ __forceinline__ void ldsm_x4(unsigned& r0, unsigned& r1, unsigned& r2, unsigned& r3,
                                        unsigned addr) {
    asm volatile("ldmatrix.sync.aligned.m8n8.x4.shared.b16 {%0,%1,%2,%3}, [%4];"
                 : "=r"(r0), "=r"(r1), "=r"(r2), "=r"(r3) : "r"(addr));
}

__device__ __forceinline__ void cp16(void* s, const void* g, bool valid) {
    unsigned saddr = (unsigned)__cvta_generic_to_shared(s);
    int sz = valid ? 16 : 0;
    asm volatile("cp.async.cg.shared.global [%0], [%1], 16, %2;" :: "r"(saddr), "l"(g), "r"(sz));
}
__device__ __forceinline__ void cp_commit() { asm volatile("cp.async.commit_group;"); }
template<int N> __device__ __forceinline__ void cp_wait() { asm volatile("cp.async.wait_group %0;" :: "n"(N)); }

// ---------- embedding body: fp16 output only ----------
template<int W0, int W1, int W2>
__device__ __forceinline__ void embed_body(int blk,
                                           const float* __restrict__ s0,
                                           const float* __restrict__ s1,
                                           const float* __restrict__ s2,
                                           const float* __restrict__ W,
                                           const float* __restrict__ bias,
                                           __half* __restrict__ out16, int n) {
    const int RB = 32;
    const int IN = W0 + W1 + W2;
    __shared__ float xs[RB][IN + 1];
    int row0 = blk * RB;
    int tid = threadIdx.x;
    int cg = tid & 63, rg = tid >> 6;

    for (int i = tid; i < RB * IN; i += 256) {
        int r = i / IN, k = i % IN;
        int row = row0 + r;
        float v = 0.f;
        if (row < n) {
            if (k < W0)            v = s0[(size_t)row * W0 + k];
            else if (k < W0 + W1)  v = s1[(size_t)row * W1 + (k - W0)];
            else                   v = s2[row];
        }
        xs[r][k] = v;
    }
    __syncthreads();

    float4 b = reinterpret_cast<const float4*>(bias)[cg];
    float4 acc[8];
#pragma unroll
    for (int q = 0; q < 8; q++) acc[q] = b;
#pragma unroll
    for (int k = 0; k < IN; k++) {
        float4 w = reinterpret_cast<const float4*>(W + (size_t)k * H)[cg];
#pragma unroll
        for (int q = 0; q < 8; q++) {
            float xv = xs[rg * 8 + q][k];
            acc[q].x += xv * w.x; acc[q].y += xv * w.y;
            acc[q].z += xv * w.z; acc[q].w += xv * w.w;
        }
    }
#pragma unroll
    for (int q = 0; q < 8; q++) {
        int row = row0 + rg * 8 + q;
        if (row < n) {
            uint2 o;
            __half2* oh = reinterpret_cast<__half2*>(&o);
            oh[0] = __floats2half2_rn(leaky(acc[q].x), leaky(acc[q].y));
            oh[1] = __floats2half2_rn(leaky(acc[q].z), leaky(acc[q].w));
            reinterpret_cast<uint2*>(out16 + (size_t)row * H)[cg] = o;
        }
    }
}

// all 4 embeddings in one launch
__global__ void embed_all(const float* __restrict__ vp,
                          const float* __restrict__ ec, const float* __restrict__ ecp,
                          const float* __restrict__ ecf,
                          const float* __restrict__ lt,
                          const float* __restrict__ fs, const float* __restrict__ fsp,
                          const float* __restrict__ fsf,
                          const float* __restrict__ Wv, const float* __restrict__ bv,
                          const float* __restrict__ We, const float* __restrict__ be,
                          const float* __restrict__ Wl, const float* __restrict__ bl,
                          const float* __restrict__ Wf, const float* __restrict__ bf,
                          __half* __restrict__ pv16, __half* __restrict__ pe16,
                          __half* __restrict__ pl16, __half* __restrict__ pf16,
                          int NVn, int NEn, int NLn, int NFn,
                          int nbv, int nbe, int nbl) {
    int b = blockIdx.x;
    if (b < nbv)                 embed_body<3, 0, 0>(b, vp, nullptr, nullptr, Wv, bv, pv16, NVn);
    else if (b < nbv + nbe)      embed_body<8, 6, 1>(b - nbv, ec, ecp, ecf, We, be, pe16, NEn);
    else if (b < nbv + nbe + nbl)embed_body<10, 0, 0>(b - nbv - nbe, lt, nullptr, nullptr, Wl, bl, pl16, NLn);
    else                         embed_body<12, 4, 1>(b - nbv - nbe - nbl, fs, fsp, fsf, Wf, bf, pf16, NFn);
}

// ---------- merged prep: weight transposes (blocks 0..383) + degree count (rest) ----------
__global__ void prep_kernel(const float* __restrict__ Wv0, const float* __restrict__ Wv1,
                            const float* __restrict__ Wv2, __half* __restrict__ Wt,
                            const int* __restrict__ d0, int n0,
                            const int* __restrict__ d1, int n1,
                            const int* __restrict__ d2, int n2,
                            int* __restrict__ cnt) {
    int b = blockIdx.x;
    if (b < 384) {
        __shared__ float tt[32][33];
        int z = b / 128, rem = b % 128;
        int bx = (rem & 15) * 32;   // k
        int by = (rem >> 4) * 32;   // n
        const float* W = (z == 0) ? Wv0 : (z == 1) ? Wv1 : Wv2;
        __half* O = Wt + (size_t)z * 512 * 256;
        int tx = threadIdx.x & 31, ty = threadIdx.x >> 5;  // 32 x 8
#pragma unroll
        for (int i = 0; i < 4; i++)
            tt[ty + i * 8][tx] = W[(size_t)(bx + ty + i * 8) * 256 + by + tx];
        __syncthreads();
#pragma unroll
        for (int i = 0; i < 4; i++)
            O[(size_t)(by + ty + i * 8) * 512 + bx + tx] = __float2half_rn(tt[tx][ty + i * 8]);
    } else {
        int i = (b - 384) * 256 + threadIdx.x;
        if (i < n0)                atomicAdd(&cnt[OFF0 + d0[i]], 1);
        else if (i < n0 + n1)      atomicAdd(&cnt[OFF1 + d1[i - n0]], 1);
        else if (i < n0 + n1 + n2) atomicAdd(&cnt[OFF2 + d2[i - n0 - n1]], 1);
    }
}

__global__ void scan_phase1(const int* __restrict__ cnt, int na, int nb_, int nc,
                            int* __restrict__ off, int* __restrict__ bsum) {
    __shared__ int wsum[32];
    int conv = blockIdx.y;
    int n = (conv == 0) ? na : (conv == 1) ? nb_ : nc;
    if (blockIdx.x * 4096 >= n) return;
    int base0 = (conv == 0) ? OFF0 : (conv == 1) ? OFF1 : OFF2;
    const int* c = cnt + base0;
    int* o = off + base0;
    int tid = threadIdx.x, lane = tid & 31, wid = tid >> 5;
    int base = blockIdx.x * 4096 + tid * 4;
    int v0 = (base     < n) ? c[base]     : 0;
    int v1 = (base + 1 < n) ? c[base + 1] : 0;
    int v2 = (base + 2 < n) ? c[base + 2] : 0;
    int v3 = (base + 3 < n) ? c[base + 3] : 0;
    int s = v0 + v1 + v2 + v3;
    int x = s;
#pragma unroll
    for (int d = 1; d < 32; d <<= 1) {
        int y = __shfl_up_sync(~0u, x, d);
        if (lane >= d) x += y;
    }
    if (lane == 31) wsum[wid] = x;
    __syncthreads();
    if (wid == 0) {
        int w = wsum[lane];
#pragma unroll
        for (int d = 1; d < 32; d <<= 1) {
            int y = __shfl_up_sync(~0u, w, d);
            if (lane >= d) w += y;
        }
        wsum[lane] = w;
    }
    __syncthreads();
    int run = x - s + (wid ? wsum[wid - 1] : 0);
    if (base     < n) o[base]     = run; run += v0;
    if (base + 1 < n) o[base + 1] = run; run += v1;
    if (base + 2 < n) o[base + 2] = run; run += v2;
    if (base + 3 < n) o[base + 3] = run;
    if (tid == 0) bsum[conv * 64 + blockIdx.x] = wsum[31];
}

__global__ void scan_phase2(int* __restrict__ bsum, int na, int nb_, int nc,
                            int* __restrict__ off) {
    __shared__ int tmp[64];
    int conv = blockIdx.x;
    int n = (conv == 0) ? na : (conv == 1) ? nb_ : nc;
    int base0 = (conv == 0) ? OFF0 : (conv == 1) ? OFF1 : OFF2;
    int* bs = bsum + conv * 64;
    int nb = (n + 4095) / 4096;
    int tid = threadIdx.x;
    int v = (tid < nb) ? bs[tid] : 0;
    tmp[tid] = v;
    __syncthreads();
    int x = v;
    for (int d = 1; d < 64; d <<= 1) {
        int y = (tid >= d) ? tmp[tid - d] : 0;
        __syncthreads();
        x += y;
        tmp[tid] = x;
        __syncthreads();
    }
    if (tid < nb) bs[tid] = x - v;
    if (tid == 63) off[base0 + n] = x;
}

__global__ void scan_phase3(int* __restrict__ off, const int* __restrict__ bsum,
                            int na, int nb_, int nc, int* __restrict__ cur) {
    int conv = blockIdx.y;
    int n = (conv == 0) ? na : (conv == 1) ? nb_ : nc;
    int i = blockIdx.x * blockDim.x + threadIdx.x;
    if (i >= n) return;
    int base0 = (conv == 0) ? OFF0 : (conv == 1) ? OFF1 : OFF2;
    int o = off[base0 + i] + bsum[conv * 64 + (i >> 12)];
    off[base0 + i] = o;
    cur[base0 + i] = o;
}

__global__ void fill_all_kernel(const int* __restrict__ e0, int n0,
                                const int* __restrict__ e1, int n1,
                                const int* __restrict__ e2, int n2,
                                int* __restrict__ cur, int* __restrict__ col) {
    int i = blockIdx.x * blockDim.x + threadIdx.x;
    const int* idx; int j, np, base0, cbase;
    if (i < n0)                { idx = e0; j = i;           np = n0; base0 = OFF0; cbase = 0; }
    else if (i < n0 + n1)      { idx = e1; j = i - n0;      np = n1; base0 = OFF1; cbase = n0; }
    else if (i < n0 + n1 + n2) { idx = e2; j = i - n0 - n1; np = n2; base0 = OFF2; cbase = n0 + n1; }
    else return;
    int d = idx[j];
    int s = idx[j + np];
    int pos = atomicAdd(&cur[base0 + d], 1);
    col[cbase + pos] = s;
}

// ---------- fused segment-min (fp16, MLP=4) + (x_dst - min) -> fp16 ----------
__global__ void segmin_csr_kernel(const int* __restrict__ off, const int* __restrict__ col,
                                  int n_dst,
                                  const __half* __restrict__ xsrc16,
                                  const __half* __restrict__ xdst16,
                                  __half* __restrict__ mh16) {
    int w = (blockIdx.x * blockDim.x + threadIdx.x) >> 5;
    int lane = threadIdx.x & 31;
    if (w >= n_dst) return;
    int beg = off[w], end = off[w + 1];
    __half2 m[4];
    const __half2 inf2 = __halves2half2(__ushort_as_half(0x7C00), __ushort_as_half(0x7C00));
#pragma unroll
    for (int q = 0; q < 4; q++) m[q] = inf2;

    for (int j = beg; j < end; j += 4) {
        int c0 = col[j];
        int c1 = (j + 1 < end) ? col[j + 1] : c0;
        int c2 = (j + 2 < end) ? col[j + 2] : c0;
        int c3 = (j + 3 < end) ? col[j + 3] : c0;
        uint4 v0 = reinterpret_cast<const uint4*>(xsrc16 + (size_t)c0 * H)[lane];
        uint4 v1 = reinterpret_cast<const uint4*>(xsrc16 + (size_t)c1 * H)[lane];
        uint4 v2 = reinterpret_cast<const uint4*>(xsrc16 + (size_t)c2 * H)[lane];
        uint4 v3 = reinterpret_cast<const uint4*>(xsrc16 + (size_t)c3 * H)[lane];
        const __half2* h0 = reinterpret_cast<const __half2*>(&v0);
        const __half2* h1 = reinterpret_cast<const __half2*>(&v1);
        const __half2* h2 = reinterpret_cast<const __half2*>(&v2);
        const __half2* h3 = reinterpret_cast<const __half2*>(&v3);
#pragma unroll
        for (int q = 0; q < 4; q++) {
            __half2 a = __hmin2(h0[q], h1[q]);
            __half2 b = __hmin2(h2[q], h3[q]);
            m[q] = __hmin2(m[q], __hmin2(a, b));
        }
    }

    uint4 xd = reinterpret_cast<const uint4*>(xdst16 + (size_t)w * H)[lane];
    const __half2* hx = reinterpret_cast<const __half2*>(&xd);
    uint4 outv;
    __half2* oh = reinterpret_cast<__half2*>(&outv);
    if (beg < end) {
#pragma unroll
        for (int q = 0; q < 4; q++) oh[q] = __hsub2(hx[q], m[q]);
    } else {
        outv = make_uint4(0, 0, 0, 0);
    }
    reinterpret_cast<uint4*>(mh16 + (size_t)w * H)[lane] = outv;
}

// ---------- fp16 tensor-core conv GEMM: 128x256 tile, 16 warps, ldmatrix, 4-stage ----------
#define BM 128
#define BK 32
#define RSTR 20                     // row stride in 32-bit words (16 used + 4 pad)
#define A_WORDS (128 * RSTR)        // 2560
#define B_WORDS (256 * RSTR)        // 5120
#define STG_WORDS (A_WORDS + B_WORDS)
#define STG_BYTES (STG_WORDS * 4)   // 30720
#define GEMM_SMEM (4 * STG_BYTES)   // 122880

__global__ __launch_bounds__(512, 1) void conv_gemm_fp16(const __half* __restrict__ x16,
                                                         const __half* __restrict__ mh16,
                                                         const __half* __restrict__ Wt16,
                                                         const float* __restrict__ bias,
                                                         float* __restrict__ out32,
                                                         __half* __restrict__ out16, int M) {
    extern __shared__ unsigned sm[];
    int tid = threadIdx.x;
    int warp = tid >> 5, lane = tid & 31;
    int g = lane >> 2, t = lane & 3;
    int wr = warp >> 2, wc = warp & 3;       // 4x4 warp grid
    int m_w = wr * 32, n_w = wc * 64;        // warp tile 32x64
    int bm = blockIdx.x * BM;

    int prow = tid >> 2;                     // 0..127
    int pc = tid & 3;

    float c[2][8][4];
#pragma unroll
    for (int i = 0; i < 2; i++)
#pragma unroll
        for (int j = 0; j < 8; j++)
#pragma unroll
            for (int q = 0; q < 4; q++) c[i][j][q] = 0.f;

    auto prefetch = [&](int tile, int slot) {
        int k0 = tile * BK;
        const __half* Ab = (k0 < 256) ? x16 : mh16;
        int kk = k0 & 255;
        unsigned* Ad = sm + slot * STG_WORDS;
        unsigned* Bd = Ad + A_WORDS;
        // A: 128 rows x 4 chunks = 512 cp -> 1 per thread
        {
            bool v = (bm + prow) < M;
            const __half* gp = Ab + (size_t)(v ? bm + prow : 0) * H + kk + pc * 8;
            cp16(Ad + prow * RSTR + pc * 4, gp, v);
        }
        // B: 256 rows x 4 chunks = 1024 cp -> 2 per thread
#pragma unroll
        for (int r = 0; r < 2; r++) {
            int row = prow + r * 128;
            cp16(Bd + row * RSTR + pc * 4,
                 Wt16 + (size_t)row * 512 + k0 + pc * 8, true);
        }
        cp_commit();
    };

    prefetch(0, 0);
    prefetch(1, 1);
    prefetch(2, 2);

    unsigned sb = (unsigned)__cvta_generic_to_shared(sm);
    unsigned aOff = (unsigned)((m_w + (lane & 15)) * RSTR) * 4 + (unsigned)(lane >> 4) * 16;
    unsigned bOff = (unsigned)A_WORDS * 4 +
                    (unsigned)((n_w + (lane & 7) + ((lane >> 4) << 3)) * RSTR) * 4 +
                    (unsigned)((lane >> 3) & 1) * 16;

    for (int it = 0; it < 16; it++) {
        if (it <= 13) cp_wait<2>();
        else if (it == 14) cp_wait<1>();
        else cp_wait<0>();
        __syncthreads();

        int slot = it & 3;
        unsigned aBase = sb + slot * STG_BYTES + aOff;
        unsigned bBase = sb + slot * STG_BYTES + bOff;
#pragma unroll
        for (int ks = 0; ks < 2; ks++) {
            unsigned kB = ks * 32;
            unsigned a[2][4], b[8][2];
#pragma unroll
            for (int i = 0; i < 2; i++)
                ldsm_x4(a[i][0], a[i][1], a[i][2], a[i][3], aBase + i * (16 * RSTR * 4) + kB);
#pragma unroll
            for (int jj = 0; jj < 4; jj++)
                ldsm_x4(b[2 * jj][0], b[2 * jj][1], b[2 * jj + 1][0], b[2 * jj + 1][1],
                        bBase + jj * (16 * RSTR * 4) + kB);
#pragma unroll
            for (int i = 0; i < 2; i++)
#pragma unroll
                for (int j = 0; j < 8; j++) mma_fp16(c[i][j], a[i], b[j]);
        }

        if (it + 3 <= 15) prefetch(it + 3, (it + 3) & 3);
    }

    // epilogue: out = x16 + leaky(c + bias)
#pragma unroll
    for (int i = 0; i < 2; i++) {
        int r0 = bm + m_w + i * 16 + g;
        int r1 = r0 + 8;
#pragma unroll
        for (int j = 0; j < 8; j++) {
            int col = n_w + j * 8 + t * 2;
            float b0 = bias[col], b1 = bias[col + 1];
            if (r0 < M) {
                size_t o = (size_t)r0 * H + col;
                float2 xf = __half22float2(*reinterpret_cast<const __half2*>(x16 + o));
                float v0 = xf.x + leaky(c[i][j][0] + b0);
                float v1 = xf.y + leaky(c[i][j][1] + b1);
                if (out32) { out32[o] = v0; out32[o + 1] = v1; }
                if (out16) *reinterpret_cast<__half2*>(out16 + o) = __floats2half2_rn(v0, v1);
            }
            if (r1 < M) {
                size_t o = (size_t)r1 * H + col;
                float2 xf = __half22float2(*reinterpret_cast<const __half2*>(x16 + o));
                float v0 = xf.x + leaky(c[i][j][2] + b0);
                float v1 = xf.y + leaky(c[i][j][3] + b1);
                if (out32) { out32[o] = v0; out32[o + 1] = v1; }
                if (out16) *reinterpret_cast<__half2*>(out16 + o) = __floats2half2_rn(v0, v1);
            }
        }
    }
}

// ---------- launch ----------
static inline int cdiv(int a, int b) { return (a + b - 1) / b; }

extern "C" void kernel_launch(void* const* d_in, const int* in_sizes, int n_in,
                              void* d_out, int out_size) {
    const float* vp  = (const float*)d_in[0];
    const float* ec  = (const float*)d_in[1];
    const float* ecp = (const float*)d_in[2];
    const float* ecf = (const float*)d_in[3];
    const float* lt  = (const float*)d_in[4];
    const float* fs  = (const float*)d_in[5];
    const float* fsp = (const float*)d_in[6];
    const float* fsf = (const float*)d_in[7];
    const int* ev = (const int*)d_in[8];
    const int* le = (const int*)d_in[9];
    const int* fl = (const int*)d_in[10];
    const float* Wv = (const float*)d_in[11]; const float* bv = (const float*)d_in[12];
    const float* We = (const float*)d_in[13]; const float* be = (const float*)d_in[14];
    const float* Wl = (const float*)d_in[15]; const float* bl = (const float*)d_in[16];
    const float* Wf = (const float*)d_in[17]; const float* bf = (const float*)d_in[18];
    const float* Wve = (const float*)d_in[19]; const float* bve = (const float*)d_in[20];
    const float* Wel = (const float*)d_in[21]; const float* bel = (const float*)d_in[22];
    const float* Wlf = (const float*)d_in[23]; const float* blf = (const float*)d_in[24];

    int NVn = in_sizes[0] / 3;
    int NEn = in_sizes[1] / 8;
    int NLn = in_sizes[4] / 10;
    int NFn = in_sizes[5] / 12;
    int nEV = in_sizes[8] / 2;
    int nLE = in_sizes[9] / 2;
    int nFL = in_sizes[10] / 2;

    __half *pv16, *pe16, *peo16, *pl16, *pf16, *pmh16, *pwt16;
    int *pcnt, *poff, *pcur, *pcol, *pbsum;
    cudaGetSymbolAddress((void**)&pv16,  g_v16);
    cudaGetSymbolAddress((void**)&pe16,  g_e16);
    cudaGetSymbolAddress((void**)&peo16, g_eo16);
    cudaGetSymbolAddress((void**)&pl16,  g_l16);
    cudaGetSymbolAddress((void**)&pf16,  g_f16);
    cudaGetSymbolAddress((void**)&pmh16, g_mh16);
    cudaGetSymbolAddress((void**)&pwt16, g_wt16);
    cudaGetSymbolAddress((void**)&pcnt,  g_cnt);
    cudaGetSymbolAddress((void**)&poff,  g_off);
    cudaGetSymbolAddress((void**)&pcur,  g_cur);
    cudaGetSymbolAddress((void**)&pcol,  g_col);
    cudaGetSymbolAddress((void**)&pbsum, g_bsum);

    cudaFuncSetAttribute(conv_gemm_fp16, cudaFuncAttributeMaxDynamicSharedMemorySize, GEMM_SMEM);

    int nPairTot = nEV + nLE + nFL;
    int nmax = NEn;

    // merged prep: weight transposes + degree counts (after memset)
    cudaMemsetAsync(pcnt, 0, (size_t)CSRTOT * sizeof(int));
    prep_kernel<<<384 + cdiv(nPairTot, 256), 256>>>(Wve, Wel, Wlf, pwt16,
                                                    ev, nEV, le, nLE, fl, nFL, pcnt);
    {
        dim3 g1(cdiv(nmax, 4096), 3);
        scan_phase1<<<g1, 1024>>>(pcnt, NEn, NLn, NFn, poff, pbsum);
        scan_phase2<<<3, 64>>>(pbsum, NEn, NLn, NFn, poff);
        dim3 g3(cdiv(nmax, 256), 3);
        scan_phase3<<<g3, 256>>>(poff, pbsum, NEn, NLn, NFn, pcur);
    }
    fill_all_kernel<<<cdiv(nPairTot, 256), 256>>>(ev, nEV, le, nLE, fl, nFL, pcur, pcol);

    // embeddings: all four in one launch, fp16 outputs only
    {
        int nbv = cdiv(NVn, 32), nbe = cdiv(NEn, 32), nbl = cdiv(NLn, 32), nbf = cdiv(NFn, 32);
        embed_all<<<nbv + nbe + nbl + nbf, 256>>>(vp, ec, ecp, ecf, lt, fs, fsp, fsf,
                                                  Wv, bv, We, be, Wl, bl, Wf, bf,
                                                  pv16, pe16, pl16, pf16,
                                                  NVn, NEn, NLn, NFn, nbv, nbe, nbl);
    }

    // conv 1: vertices -> edges
    segmin_csr_kernel<<<cdiv(NEn * 32, 256), 256>>>(poff + OFF0, pcol, NEn, pv16, pe16, pmh16);
    conv_gemm_fp16<<<cdiv(NEn, BM), 512, GEMM_SMEM>>>(pe16, pmh16, pwt16, bve, nullptr, peo16, NEn);

    // conv 2: edges -> loops (fp16 out reuses g_v16)
    segmin_csr_kernel<<<cdiv(NLn * 32, 256), 256>>>(poff + OFF1, pcol + nEV, NLn, peo16, pl16, pmh16);
    conv_gemm_fp16<<<cdiv(NLn, BM), 512, GEMM_SMEM>>>(pl16, pmh16, pwt16 + 512 * 256, bel, nullptr, pv16, NLn);

    // conv 3: loops -> faces (fp32 output = d_out)
    segmin_csr_kernel<<<cdiv(NFn * 32, 256), 256>>>(poff + OFF2, pcol + nEV + nLE, NFn, pv16, pf16, pmh16);
    conv_gemm_fp16<<<cdiv(NFn, BM), 512, GEMM_SMEM>>>(pf16, pmh16, pwt16 + 2 * 512 * 256, blf, (float*)d_out, nullptr, NFn);
}